// round 1
// baseline (speedup 1.0000x reference)
#include <cuda_runtime.h>

// ---------------------------------------------------------------------------
// GNNEncoder: 3x GCNConv(relu) -> sum of layer outputs -> global_mean_pool -> MLP
// Strategy: build dst-sorted CSR once per launch (counting sort), then each
// GCN layer = warp-per-row GEMM (W in smem) + warp-per-dst CSR aggregate with
// fused self-loop, bias, ReLU and running hsum. No per-feature atomics.
// ---------------------------------------------------------------------------

#define NMAX 50000
#define EMAX 800000
#define GMAX 2500
#define F 64

__device__ int   g_cnt[NMAX];         // per-dst edge count (histogram)
__device__ int   g_rowptr[NMAX + 1];  // CSR row pointers (by dst)
__device__ int   g_cursor[NMAX];      // fill cursors
__device__ float g_dis[NMAX];         // deg^-1/2
__device__ float g_dis2[NMAX];        // deg^-1 (self-loop norm)
__device__ int   g_esrc[EMAX];        // CSR: src node per edge
__device__ float g_enorm[EMAX];       // CSR: norm per edge
__device__ float g_h[NMAX * F];       // GEMM output (messages)
__device__ float g_xb[NMAX * F];      // layer activation buffer
__device__ float g_hsum[NMAX * F];    // x1 + x2 + x3
__device__ float g_pool[GMAX * F];    // per-graph feature sums
__device__ float g_pcnt[GMAX];        // per-graph node counts

// ---------------- graph preprocessing ----------------

__global__ void k_zero_cnt(int n) {
    int i = blockIdx.x * blockDim.x + threadIdx.x;
    if (i < n) g_cnt[i] = 0;
}

__global__ void k_hist(const int* __restrict__ dst, int E) {
    int e = blockIdx.x * blockDim.x + threadIdx.x;
    if (e < E) atomicAdd(&g_cnt[dst[e]], 1);
}

__global__ void k_dis(int n) {
    int i = blockIdx.x * blockDim.x + threadIdx.x;
    if (i < n) {
        float deg = (float)(g_cnt[i] + 1);   // +1 self loop
        g_dis[i]  = rsqrtf(deg);
        g_dis2[i] = 1.0f / deg;
    }
}

// single-block exclusive scan of g_cnt -> g_rowptr (and g_cursor copy)
__global__ void k_scan(int n) {
    __shared__ int sh[1024];
    __shared__ int s_carry;
    if (threadIdx.x == 0) s_carry = 0;
    __syncthreads();
    for (int base = 0; base < n; base += 1024) {
        int i = base + threadIdx.x;
        int v = (i < n) ? g_cnt[i] : 0;
        sh[threadIdx.x] = v;
        __syncthreads();
        for (int off = 1; off < 1024; off <<= 1) {
            int t = (threadIdx.x >= (unsigned)off) ? sh[threadIdx.x - off] : 0;
            __syncthreads();
            sh[threadIdx.x] += t;
            __syncthreads();
        }
        int carry = s_carry;
        int excl = carry + sh[threadIdx.x] - v;
        if (i < n) { g_rowptr[i] = excl; g_cursor[i] = excl; }
        __syncthreads();
        if (threadIdx.x == 1023) s_carry = carry + sh[1023];
        __syncthreads();
    }
    if (threadIdx.x == 0) g_rowptr[n] = s_carry;
}

__global__ void k_fill(const int* __restrict__ src, const int* __restrict__ dst, int E) {
    int e = blockIdx.x * blockDim.x + threadIdx.x;
    if (e >= E) return;
    int s = src[e], d = dst[e];
    float nm = g_dis[s] * g_dis[d];
    int pos = atomicAdd(&g_cursor[d], 1);
    g_esrc[pos]  = s;
    g_enorm[pos] = nm;
}

// ---------------- GEMM: H[n,64] = X[n,K] @ W[K,64] (warp per row) ----------

__global__ void k_gemm(const float* __restrict__ X, const float* __restrict__ W,
                       float* __restrict__ H, int n, int K) {
    extern __shared__ float Ws[];
    for (int i = threadIdx.x; i < K * F; i += blockDim.x) Ws[i] = W[i];
    __syncthreads();
    int w = (blockIdx.x * blockDim.x + threadIdx.x) >> 5;
    int lane = threadIdx.x & 31;
    if (w >= n) return;
    const float* xr = X + (long long)w * K;
    float a0 = 0.f, a1 = 0.f;
#pragma unroll 8
    for (int k = 0; k < K; k++) {
        float xv = __ldg(&xr[k]);
        a0 += xv * Ws[k * F + lane];
        a1 += xv * Ws[k * F + 32 + lane];
    }
    long long o = (long long)w * F;
    H[o + lane] = a0;
    H[o + 32 + lane] = a1;
}

// ---------------- CSR aggregate: warp per dst node --------------------------
// out[d] = relu( sum_{e: dst==d} norm_e * h[src_e] + dis2[d]*h[d] + b )
// also maintains g_hsum (= for first layer, += otherwise)

__global__ void k_agg(const float* __restrict__ h, const float* __restrict__ b,
                      float* __restrict__ xout, int n, int first) {
    int w = (blockIdx.x * blockDim.x + threadIdx.x) >> 5;
    int lane = threadIdx.x & 31;
    if (w >= n) return;
    float self = g_dis2[w];
    long long o = (long long)w * F;
    float a0 = h[o + lane] * self;
    float a1 = h[o + 32 + lane] * self;
    int beg = g_rowptr[w], end = g_rowptr[w + 1];
    for (int k = beg; k < end; k++) {
        int s = g_esrc[k];
        float nm = g_enorm[k];
        long long so = (long long)s * F;
        a0 += nm * h[so + lane];
        a1 += nm * h[so + 32 + lane];
    }
    a0 = fmaxf(a0 + __ldg(&b[lane]), 0.f);
    a1 = fmaxf(a1 + __ldg(&b[32 + lane]), 0.f);
    xout[o + lane] = a0;
    xout[o + 32 + lane] = a1;
    if (first) {
        g_hsum[o + lane] = a0;
        g_hsum[o + 32 + lane] = a1;
    } else {
        g_hsum[o + lane] += a0;
        g_hsum[o + 32 + lane] += a1;
    }
}

// ---------------- pooling + MLP ---------------------------------------------

__global__ void k_zero_pool(int G) {
    int t = blockIdx.x * blockDim.x + threadIdx.x;
    if (t < G * F) g_pool[t] = 0.f;
    if (t < G) g_pcnt[t] = 0.f;
}

__global__ void k_pool(const int* __restrict__ batch, int n) {
    int t = blockIdx.x * blockDim.x + threadIdx.x;
    if (t >= n * 16) return;
    int node = t >> 4, lane = t & 15;
    int g = batch[node];
    float4 v = ((const float4*)g_hsum)[t];
    float* o = g_pool + g * F + lane * 4;
    atomicAdd(o + 0, v.x);
    atomicAdd(o + 1, v.y);
    atomicAdd(o + 2, v.z);
    atomicAdd(o + 3, v.w);
    if (lane == 0) atomicAdd(&g_pcnt[g], 1.0f);
}

__global__ void k_mlp(const float* __restrict__ Wp1, const float* __restrict__ bp1,
                      const float* __restrict__ Wp2, const float* __restrict__ bp2,
                      float* __restrict__ out) {
    __shared__ float p[F], t1[F];
    int g = blockIdx.x, j = threadIdx.x;
    float inv = 1.0f / fmaxf(g_pcnt[g], 1.0f);
    p[j] = g_pool[g * F + j] * inv;
    __syncthreads();
    float acc = bp1[j];
#pragma unroll
    for (int k = 0; k < F; k++) acc += p[k] * Wp1[k * F + j];
    t1[j] = fmaxf(acc, 0.f);
    __syncthreads();
    if (j < 32) {
        float acc2 = bp2[j];
#pragma unroll
        for (int k = 0; k < F; k++) acc2 += t1[k] * Wp2[k * 32 + j];
        out[g * 32 + j] = acc2;
    }
}

// ---------------- launch -----------------------------------------------------

extern "C" void kernel_launch(void* const* d_in, const int* in_sizes, int n_in,
                              void* d_out, int out_size) {
    const float* x    = (const float*)d_in[0];
    const int*   ei   = (const int*)d_in[1];
    const int*   batch= (const int*)d_in[2];
    const float* W1   = (const float*)d_in[3];
    const float* b1   = (const float*)d_in[4];
    const float* W2   = (const float*)d_in[5];
    const float* b2   = (const float*)d_in[6];
    const float* W3   = (const float*)d_in[7];
    const float* b3   = (const float*)d_in[8];
    const float* Wp1  = (const float*)d_in[9];
    const float* bp1  = (const float*)d_in[10];
    const float* Wp2  = (const float*)d_in[11];
    const float* bp2  = (const float*)d_in[12];
    float* out = (float*)d_out;

    int N = in_sizes[0] / 128;
    int E = in_sizes[1] / 2;
    int G = out_size / 32;
    const int* src = ei;
    const int* dst = ei + E;

    float *p_h, *p_xb;
    cudaGetSymbolAddress((void**)&p_h, g_h);
    cudaGetSymbolAddress((void**)&p_xb, g_xb);

    const int T = 256;

    // graph preprocessing (CSR by dst + norms)
    k_zero_cnt<<<(N + T - 1) / T, T>>>(N);
    k_hist<<<(E + T - 1) / T, T>>>(dst, E);
    k_dis<<<(N + T - 1) / T, T>>>(N);
    k_scan<<<1, 1024>>>(N);
    k_fill<<<(E + T - 1) / T, T>>>(src, dst, E);

    int gemm_blocks = (N + 7) / 8;    // 8 warps (rows) per 256-thread block
    int agg_blocks  = (N + 7) / 8;

    // layer 1
    k_gemm<<<gemm_blocks, T, 128 * F * sizeof(float)>>>(x, W1, p_h, N, 128);
    k_agg<<<agg_blocks, T>>>(p_h, b1, p_xb, N, 1);
    // layer 2
    k_gemm<<<gemm_blocks, T, 64 * F * sizeof(float)>>>(p_xb, W2, p_h, N, 64);
    k_agg<<<agg_blocks, T>>>(p_h, b2, p_xb, N, 0);
    // layer 3
    k_gemm<<<gemm_blocks, T, 64 * F * sizeof(float)>>>(p_xb, W3, p_h, N, 64);
    k_agg<<<agg_blocks, T>>>(p_h, b3, p_xb, N, 0);

    // pooling + MLP
    k_zero_pool<<<(G * F + T - 1) / T, T>>>(G);
    k_pool<<<(N * 16 + T - 1) / T, T>>>(batch, N);
    k_mlp<<<G, F>>>(Wp1, bp1, Wp2, bp2, out);
}

// round 2
// speedup vs baseline: 1.8687x; 1.8687x over previous
#include <cuda_runtime.h>

// ---------------------------------------------------------------------------
// GNNEncoder: 3x GCNConv(relu) -> sum of layer outputs -> global_mean_pool -> MLP
// R2: multi-block scan (was 81us single-block), 4-row/warp shfl-broadcast GEMM,
// packed (src,norm) edges + unrolled agg, fused pool+MLP via binary search.
// ---------------------------------------------------------------------------

#define NMAX 50000
#define EMAX 800000
#define GMAX 2500
#define F 64
#define SCAN_B 1024
#define NBLK_MAX ((NMAX + SCAN_B - 1) / SCAN_B + 1)

__device__ int   g_cnt[NMAX];         // per-dst edge count (histogram)
__device__ int   g_rowptr[NMAX + 1];  // CSR row pointers (by dst)
__device__ int   g_cursor[NMAX];      // fill cursors
__device__ float g_dis[NMAX];         // deg^-1/2
__device__ float g_dis2[NMAX];        // deg^-1 (self-loop norm)
__device__ int2  g_epack[EMAX];       // CSR: (src, norm-bits) per edge
__device__ int   g_bsum[NBLK_MAX];    // scan block sums
__device__ int   g_boff[NBLK_MAX];    // scan block offsets
__device__ float g_h[NMAX * F];       // GEMM output (messages)
__device__ float g_xb[NMAX * F];      // layer activation buffer
__device__ float g_hsum[NMAX * F];    // x1 + x2 + x3

// ---------------- graph preprocessing ----------------

__global__ void k_zero_cnt(int n) {
    int i = blockIdx.x * blockDim.x + threadIdx.x;
    if (i < n) g_cnt[i] = 0;
}

__global__ void k_hist(const int* __restrict__ dst, int E) {
    int e = blockIdx.x * blockDim.x + threadIdx.x;
    if (e < E) atomicAdd(&g_cnt[dst[e]], 1);
}

__global__ void k_dis(int n) {
    int i = blockIdx.x * blockDim.x + threadIdx.x;
    if (i < n) {
        float deg = (float)(g_cnt[i] + 1);   // +1 self loop
        g_dis[i]  = rsqrtf(deg);
        g_dis2[i] = 1.0f / deg;
    }
}

// Phase A: per-block inclusive scan of g_cnt -> g_rowptr (local), block totals.
__global__ void k_scan_local(int n) {
    __shared__ int wsum[32];
    int i = blockIdx.x * SCAN_B + threadIdx.x;
    int lane = threadIdx.x & 31, wid = threadIdx.x >> 5;
    int v = (i < n) ? g_cnt[i] : 0;
    int s = v;
#pragma unroll
    for (int o = 1; o < 32; o <<= 1) {
        int t = __shfl_up_sync(0xffffffffu, s, o);
        if (lane >= o) s += t;
    }
    if (lane == 31) wsum[wid] = s;
    __syncthreads();
    if (wid == 0) {
        int ws = wsum[lane];
#pragma unroll
        for (int o = 1; o < 32; o <<= 1) {
            int t = __shfl_up_sync(0xffffffffu, ws, o);
            if (lane >= o) ws += t;
        }
        wsum[lane] = ws;
    }
    __syncthreads();
    int incl = s + (wid > 0 ? wsum[wid - 1] : 0);
    if (i < n) g_rowptr[i] = incl;           // temp: local inclusive
    if (threadIdx.x == SCAN_B - 1) g_bsum[blockIdx.x] = incl;
}

// Phase B: serial exclusive scan of block sums (nb <= 49) + total rowptr[n].
__global__ void k_scan_bsum(int nb, int n) {
    int run = 0;
    for (int i = 0; i < nb; i++) {
        g_boff[i] = run;
        run += g_bsum[i];
    }
    g_rowptr[n] = run;
}

// Phase C: finalize exclusive scan + cursors.
__global__ void k_scan_final(int n) {
    int i = blockIdx.x * SCAN_B + threadIdx.x;
    if (i >= n) return;
    int excl = g_boff[blockIdx.x] + g_rowptr[i] - g_cnt[i];
    g_rowptr[i] = excl;
    g_cursor[i] = excl;
}

__global__ void k_fill(const int* __restrict__ src, const int* __restrict__ dst, int E) {
    int e = blockIdx.x * blockDim.x + threadIdx.x;
    if (e >= E) return;
    int s = src[e], d = dst[e];
    float nm = g_dis[s] * g_dis[d];
    int pos = atomicAdd(&g_cursor[d], 1);
    g_epack[pos] = make_int2(s, __float_as_int(nm));
}

// ---------------- GEMM: H[n,64] = X[n,K] @ W[K,64] --------------------------
// 4 rows per warp; X loaded coalesced and broadcast via shfl; W in smem.

__global__ void k_gemm4(const float* __restrict__ X, const float* __restrict__ W,
                        float* __restrict__ H, int n, int K) {
    extern __shared__ float Ws[];
    for (int i = threadIdx.x; i < K * F; i += blockDim.x) Ws[i] = W[i];
    __syncthreads();
    int warp = (blockIdx.x * blockDim.x + threadIdx.x) >> 5;
    int lane = threadIdx.x & 31;
    int r0 = warp * 4;
    if (r0 >= n) return;
    int nr = n - r0; if (nr > 4) nr = 4;

    float a00 = 0.f, a01 = 0.f, a10 = 0.f, a11 = 0.f;
    float a20 = 0.f, a21 = 0.f, a30 = 0.f, a31 = 0.f;

    for (int kb = 0; kb < K; kb += 32) {
        float x0 = (0 < nr) ? __ldg(&X[(size_t)(r0 + 0) * K + kb + lane]) : 0.f;
        float x1 = (1 < nr) ? __ldg(&X[(size_t)(r0 + 1) * K + kb + lane]) : 0.f;
        float x2 = (2 < nr) ? __ldg(&X[(size_t)(r0 + 2) * K + kb + lane]) : 0.f;
        float x3 = (3 < nr) ? __ldg(&X[(size_t)(r0 + 3) * K + kb + lane]) : 0.f;
#pragma unroll
        for (int kk = 0; kk < 32; kk++) {
            float w0 = Ws[(kb + kk) * F + lane];
            float w1 = Ws[(kb + kk) * F + 32 + lane];
            float b0 = __shfl_sync(0xffffffffu, x0, kk);
            float b1 = __shfl_sync(0xffffffffu, x1, kk);
            float b2 = __shfl_sync(0xffffffffu, x2, kk);
            float b3 = __shfl_sync(0xffffffffu, x3, kk);
            a00 += b0 * w0; a01 += b0 * w1;
            a10 += b1 * w0; a11 += b1 * w1;
            a20 += b2 * w0; a21 += b2 * w1;
            a30 += b3 * w0; a31 += b3 * w1;
        }
    }
    size_t o = (size_t)r0 * F;
    H[o + lane] = a00; H[o + 32 + lane] = a01;
    if (1 < nr) { H[o + F + lane] = a10; H[o + F + 32 + lane] = a11; }
    if (2 < nr) { H[o + 2 * F + lane] = a20; H[o + 2 * F + 32 + lane] = a21; }
    if (3 < nr) { H[o + 3 * F + lane] = a30; H[o + 3 * F + 32 + lane] = a31; }
}

// ---------------- CSR aggregate: warp per dst node --------------------------
// out[d] = relu( sum_{e: dst==d} norm_e * h[src_e] + dis2[d]*h[d] + b )
// also maintains g_hsum (= for first layer, += otherwise)

__global__ void k_agg(const float* __restrict__ h, const float* __restrict__ b,
                      float* __restrict__ xout, int n, int first) {
    int w = (blockIdx.x * blockDim.x + threadIdx.x) >> 5;
    int lane = threadIdx.x & 31;
    if (w >= n) return;
    float self = g_dis2[w];
    size_t o = (size_t)w * F;
    float a0 = h[o + lane] * self;
    float a1 = h[o + 32 + lane] * self;
    int beg = g_rowptr[w], end = g_rowptr[w + 1];
    int k = beg;
    for (; k + 1 < end; k += 2) {
        int2 e0 = g_epack[k];
        int2 e1 = g_epack[k + 1];
        float n0 = __int_as_float(e0.y);
        float n1 = __int_as_float(e1.y);
        const float* h0 = h + (size_t)e0.x * F;
        const float* h1 = h + (size_t)e1.x * F;
        float v00 = h0[lane], v01 = h0[32 + lane];
        float v10 = h1[lane], v11 = h1[32 + lane];
        a0 += n0 * v00; a1 += n0 * v01;
        a0 += n1 * v10; a1 += n1 * v11;
    }
    if (k < end) {
        int2 e0 = g_epack[k];
        float n0 = __int_as_float(e0.y);
        const float* h0 = h + (size_t)e0.x * F;
        a0 += n0 * h0[lane]; a1 += n0 * h0[32 + lane];
    }
    a0 = fmaxf(a0 + __ldg(&b[lane]), 0.f);
    a1 = fmaxf(a1 + __ldg(&b[32 + lane]), 0.f);
    xout[o + lane] = a0;
    xout[o + 32 + lane] = a1;
    if (first) {
        g_hsum[o + lane] = a0;
        g_hsum[o + 32 + lane] = a1;
    } else {
        g_hsum[o + lane] += a0;
        g_hsum[o + 32 + lane] += a1;
    }
}

// ---------------- fused pool + MLP -------------------------------------------
// batch is sorted: per-graph node range via binary search; 64-thread block per
// graph reduces g_hsum coalesced, then runs the 2-layer MLP in smem.

__device__ __forceinline__ int lower_bound_i(const int* __restrict__ a, int n, int key) {
    int lo = 0, hi = n;
    while (lo < hi) {
        int mid = (lo + hi) >> 1;
        if (a[mid] < key) lo = mid + 1; else hi = mid;
    }
    return lo;
}

__global__ void k_poolmlp(const int* __restrict__ batch, int n,
                          const float* __restrict__ Wp1, const float* __restrict__ bp1,
                          const float* __restrict__ Wp2, const float* __restrict__ bp2,
                          float* __restrict__ out) {
    __shared__ int s_range[2];
    __shared__ float p[F], t1[F];
    int g = blockIdx.x, j = threadIdx.x;
    if (j < 2) s_range[j] = lower_bound_i(batch, n, g + j);
    __syncthreads();
    int st = s_range[0], en = s_range[1];
    float acc = 0.f;
    for (int node = st; node < en; node++)
        acc += g_hsum[(size_t)node * F + j];
    float inv = 1.0f / fmaxf((float)(en - st), 1.0f);
    p[j] = acc * inv;
    __syncthreads();
    float a = bp1[j];
#pragma unroll
    for (int k = 0; k < F; k++) a += p[k] * Wp1[k * F + j];
    t1[j] = fmaxf(a, 0.f);
    __syncthreads();
    if (j < 32) {
        float a2 = bp2[j];
#pragma unroll
        for (int k = 0; k < F; k++) a2 += t1[k] * Wp2[k * 32 + j];
        out[g * 32 + j] = a2;
    }
}

// ---------------- launch -----------------------------------------------------

extern "C" void kernel_launch(void* const* d_in, const int* in_sizes, int n_in,
                              void* d_out, int out_size) {
    const float* x    = (const float*)d_in[0];
    const int*   ei   = (const int*)d_in[1];
    const int*   batch= (const int*)d_in[2];
    const float* W1   = (const float*)d_in[3];
    const float* b1   = (const float*)d_in[4];
    const float* W2   = (const float*)d_in[5];
    const float* b2   = (const float*)d_in[6];
    const float* W3   = (const float*)d_in[7];
    const float* b3   = (const float*)d_in[8];
    const float* Wp1  = (const float*)d_in[9];
    const float* bp1  = (const float*)d_in[10];
    const float* Wp2  = (const float*)d_in[11];
    const float* bp2  = (const float*)d_in[12];
    float* out = (float*)d_out;

    int N = in_sizes[0] / 128;
    int E = in_sizes[1] / 2;
    int G = out_size / 32;
    const int* src = ei;
    const int* dst = ei + E;

    float *p_h, *p_xb;
    cudaGetSymbolAddress((void**)&p_h, g_h);
    cudaGetSymbolAddress((void**)&p_xb, g_xb);

    const int T = 256;
    int nblk = (N + SCAN_B - 1) / SCAN_B;

    // graph preprocessing (CSR by dst + norms)
    k_zero_cnt<<<(N + T - 1) / T, T>>>(N);
    k_hist<<<(E + T - 1) / T, T>>>(dst, E);
    k_dis<<<(N + T - 1) / T, T>>>(N);
    k_scan_local<<<nblk, SCAN_B>>>(N);
    k_scan_bsum<<<1, 1>>>(nblk, N);
    k_scan_final<<<nblk, SCAN_B>>>(N);
    k_fill<<<(E + T - 1) / T, T>>>(src, dst, E);

    int gemm_blocks = (N + 31) / 32;  // 8 warps x 4 rows per 256-thread block
    int agg_blocks  = (N + 7) / 8;

    // layer 1
    k_gemm4<<<gemm_blocks, T, 128 * F * sizeof(float)>>>(x, W1, p_h, N, 128);
    k_agg<<<agg_blocks, T>>>(p_h, b1, p_xb, N, 1);
    // layer 2
    k_gemm4<<<gemm_blocks, T, 64 * F * sizeof(float)>>>(p_xb, W2, p_h, N, 64);
    k_agg<<<agg_blocks, T>>>(p_h, b2, p_xb, N, 0);
    // layer 3
    k_gemm4<<<gemm_blocks, T, 64 * F * sizeof(float)>>>(p_xb, W3, p_h, N, 64);
    k_agg<<<agg_blocks, T>>>(p_h, b3, p_xb, N, 0);

    // fused pooling + MLP
    k_poolmlp<<<G, F>>>(batch, N, Wp1, bp1, Wp2, bp2, out);
}

// round 3
// speedup vs baseline: 2.2952x; 1.2282x over previous
#include <cuda_runtime.h>

// ---------------------------------------------------------------------------
// GNNEncoder: 3x GCNConv(relu) -> sum of layer outputs -> global_mean_pool -> MLP
// R3: float4 half-warp aggregate (1 LDG.128 per edge-pair), tiled 64x64 GEMM
// with 4x4 register blocking, dis folded into scan.
// ---------------------------------------------------------------------------

#define NMAX 50000
#define EMAX 800000
#define GMAX 2500
#define F 64
#define SCAN_B 1024
#define NBLK_MAX ((NMAX + SCAN_B - 1) / SCAN_B + 1)

__device__ int   g_cnt[NMAX];
__device__ int   g_rowptr[NMAX + 1];
__device__ int   g_cursor[NMAX];
__device__ float g_dis[NMAX];
__device__ float g_dis2[NMAX];
__device__ int2  g_epack[EMAX];
__device__ int   g_bsum[NBLK_MAX];
__device__ int   g_boff[NBLK_MAX];
__device__ float g_h[NMAX * F];
__device__ float g_xb[NMAX * F];
__device__ float g_hsum[NMAX * F];

// ---------------- graph preprocessing ----------------

__global__ void k_zero_cnt(int n) {
    int i = blockIdx.x * blockDim.x + threadIdx.x;
    if (i < n) g_cnt[i] = 0;
}

__global__ void k_hist(const int* __restrict__ dst, int E) {
    int e = blockIdx.x * blockDim.x + threadIdx.x;
    if (e < E) atomicAdd(&g_cnt[dst[e]], 1);
}

// Phase A: per-block inclusive scan of g_cnt -> g_rowptr; also dis/dis2.
__global__ void k_scan_local(int n) {
    __shared__ int wsum[32];
    int i = blockIdx.x * SCAN_B + threadIdx.x;
    int lane = threadIdx.x & 31, wid = threadIdx.x >> 5;
    int v = (i < n) ? g_cnt[i] : 0;
    if (i < n) {
        float deg = (float)(v + 1);
        g_dis[i]  = rsqrtf(deg);
        g_dis2[i] = 1.0f / deg;
    }
    int s = v;
#pragma unroll
    for (int o = 1; o < 32; o <<= 1) {
        int t = __shfl_up_sync(0xffffffffu, s, o);
        if (lane >= o) s += t;
    }
    if (lane == 31) wsum[wid] = s;
    __syncthreads();
    if (wid == 0) {
        int ws = wsum[lane];
#pragma unroll
        for (int o = 1; o < 32; o <<= 1) {
            int t = __shfl_up_sync(0xffffffffu, ws, o);
            if (lane >= o) ws += t;
        }
        wsum[lane] = ws;
    }
    __syncthreads();
    int incl = s + (wid > 0 ? wsum[wid - 1] : 0);
    if (i < n) g_rowptr[i] = incl;
    if (threadIdx.x == SCAN_B - 1) g_bsum[blockIdx.x] = incl;
}

__global__ void k_scan_bsum(int nb, int n) {
    int run = 0;
    for (int i = 0; i < nb; i++) { g_boff[i] = run; run += g_bsum[i]; }
    g_rowptr[n] = run;
}

__global__ void k_scan_final(int n) {
    int i = blockIdx.x * SCAN_B + threadIdx.x;
    if (i >= n) return;
    int excl = g_boff[blockIdx.x] + g_rowptr[i] - g_cnt[i];
    g_rowptr[i] = excl;
    g_cursor[i] = excl;
}

__global__ void k_fill(const int* __restrict__ src, const int* __restrict__ dst, int E) {
    int e = blockIdx.x * blockDim.x + threadIdx.x;
    if (e >= E) return;
    int s = src[e], d = dst[e];
    float nm = g_dis[s] * g_dis[d];
    int pos = atomicAdd(&g_cursor[d], 1);
    g_epack[pos] = make_int2(s, __float_as_int(nm));
}

// ---------------- GEMM: H[n,64] = X[n,K] @ W[K,64], tiled 64x64, 4x4/thread --

#define BM 64
#define BK 16

__global__ void k_gemm_t(const float* __restrict__ X, const float* __restrict__ W,
                         float* __restrict__ H, int n, int K) {
    __shared__ float As[BK][BM];   // transposed A tile (k-major rows, 256B stride)
    __shared__ float Bs[BK][F];
    int tx = threadIdx.x & 15;     // output col quad: cols tx*4..tx*4+3
    int ty = threadIdx.x >> 4;     // output row quad: rows ty*4..ty*4+3
    int row0 = blockIdx.x * BM;

    float acc[4][4] = {};

    for (int kb = 0; kb < K; kb += BK) {
        // A tile: 64 rows x 16 cols; thread t loads float4 of row (t>>2)
        {
            int r  = threadIdx.x >> 2;
            int c4 = (threadIdx.x & 3) * 4;
            float4 v = make_float4(0.f, 0.f, 0.f, 0.f);
            if (row0 + r < n)
                v = *(const float4*)&X[(size_t)(row0 + r) * K + kb + c4];
            As[c4 + 0][r] = v.x; As[c4 + 1][r] = v.y;
            As[c4 + 2][r] = v.z; As[c4 + 3][r] = v.w;
        }
        // B tile: 16 x 64; thread t loads float4 of row (t>>4)
        {
            int r = threadIdx.x >> 4;
            int c = (threadIdx.x & 15) * 4;
            *(float4*)&Bs[r][c] = *(const float4*)&W[(size_t)(kb + r) * F + c];
        }
        __syncthreads();
#pragma unroll
        for (int k = 0; k < BK; k++) {
            float4 a = *(const float4*)&As[k][ty * 4];
            float4 b = *(const float4*)&Bs[k][tx * 4];
            float av[4] = {a.x, a.y, a.z, a.w};
            float bv[4] = {b.x, b.y, b.z, b.w};
#pragma unroll
            for (int i = 0; i < 4; i++)
#pragma unroll
                for (int j = 0; j < 4; j++)
                    acc[i][j] += av[i] * bv[j];
        }
        __syncthreads();
    }
#pragma unroll
    for (int i = 0; i < 4; i++) {
        int r = row0 + ty * 4 + i;
        if (r < n)
            *(float4*)&H[(size_t)r * F + tx * 4] =
                make_float4(acc[i][0], acc[i][1], acc[i][2], acc[i][3]);
    }
}

// ---------------- CSR aggregate: warp per dst, half-warp per edge -----------
// Features: 16 lanes x float4 = 64. Lanes 0-15 (half 0) process even edges,
// lanes 16-31 (half 1) odd edges; combine via shfl_xor(16). Half 0 writes
// xout, half 1 writes hsum.

__global__ void k_agg(const float* __restrict__ h, const float* __restrict__ b,
                      float* __restrict__ xout, int n, int first) {
    int w = (blockIdx.x * blockDim.x + threadIdx.x) >> 5;
    int lane = threadIdx.x & 31;
    if (w >= n) return;
    int half = lane >> 4;
    int fl = lane & 15;

    float4 acc = make_float4(0.f, 0.f, 0.f, 0.f);
    int beg = g_rowptr[w], end = g_rowptr[w + 1];
    int k = beg;

    // 4 edges / iteration (2 per half)
    for (; k + 4 <= end; k += 4) {
        int2 e0 = g_epack[k + half];
        int2 e1 = g_epack[k + 2 + half];
        float n0 = __int_as_float(e0.y);
        float n1 = __int_as_float(e1.y);
        float4 v0 = __ldg((const float4*)(h + (size_t)e0.x * F) + fl);
        float4 v1 = __ldg((const float4*)(h + (size_t)e1.x * F) + fl);
        acc.x += n0 * v0.x + n1 * v1.x;
        acc.y += n0 * v0.y + n1 * v1.y;
        acc.z += n0 * v0.z + n1 * v1.z;
        acc.w += n0 * v0.w + n1 * v1.w;
    }
    // 2 edges
    if (k + 2 <= end) {
        int2 e0 = g_epack[k + half];
        float n0 = __int_as_float(e0.y);
        float4 v0 = __ldg((const float4*)(h + (size_t)e0.x * F) + fl);
        acc.x += n0 * v0.x; acc.y += n0 * v0.y;
        acc.z += n0 * v0.z; acc.w += n0 * v0.w;
        k += 2;
    }
    // last odd edge (half 0 only)
    if (k < end && half == 0) {
        int2 e0 = g_epack[k];
        float n0 = __int_as_float(e0.y);
        float4 v0 = __ldg((const float4*)(h + (size_t)e0.x * F) + fl);
        acc.x += n0 * v0.x; acc.y += n0 * v0.y;
        acc.z += n0 * v0.z; acc.w += n0 * v0.w;
    }
    // combine halves
    acc.x += __shfl_xor_sync(0xffffffffu, acc.x, 16);
    acc.y += __shfl_xor_sync(0xffffffffu, acc.y, 16);
    acc.z += __shfl_xor_sync(0xffffffffu, acc.z, 16);
    acc.w += __shfl_xor_sync(0xffffffffu, acc.w, 16);

    // self loop + bias + relu
    float self = g_dis2[w];
    const float4* hp = (const float4*)(h + (size_t)w * F);
    float4 hs = hp[fl];
    float4 bv = __ldg((const float4*)b + fl);
    float4 r;
    r.x = fmaxf(acc.x + self * hs.x + bv.x, 0.f);
    r.y = fmaxf(acc.y + self * hs.y + bv.y, 0.f);
    r.z = fmaxf(acc.z + self * hs.z + bv.z, 0.f);
    r.w = fmaxf(acc.w + self * hs.w + bv.w, 0.f);

    float4* xo = (float4*)(xout + (size_t)w * F);
    float4* hsu = (float4*)(g_hsum + (size_t)w * F);
    if (half == 0) {
        xo[fl] = r;
    } else {
        if (first) {
            hsu[fl] = r;
        } else {
            float4 old = hsu[fl];
            old.x += r.x; old.y += r.y; old.z += r.z; old.w += r.w;
            hsu[fl] = old;
        }
    }
}

// ---------------- fused pool + MLP ------------------------------------------

__device__ __forceinline__ int lower_bound_i(const int* __restrict__ a, int n, int key) {
    int lo = 0, hi = n;
    while (lo < hi) {
        int mid = (lo + hi) >> 1;
        if (a[mid] < key) lo = mid + 1; else hi = mid;
    }
    return lo;
}

__global__ void k_poolmlp(const int* __restrict__ batch, int n,
                          const float* __restrict__ Wp1, const float* __restrict__ bp1,
                          const float* __restrict__ Wp2, const float* __restrict__ bp2,
                          float* __restrict__ out) {
    __shared__ int s_range[2];
    __shared__ float p[F], t1[F];
    int g = blockIdx.x, j = threadIdx.x;
    if (j < 2) s_range[j] = lower_bound_i(batch, n, g + j);
    __syncthreads();
    int st = s_range[0], en = s_range[1];
    float acc = 0.f;
    for (int node = st; node < en; node++)
        acc += g_hsum[(size_t)node * F + j];
    float inv = 1.0f / fmaxf((float)(en - st), 1.0f);
    p[j] = acc * inv;
    __syncthreads();
    float a = bp1[j];
#pragma unroll
    for (int k = 0; k < F; k++) a += p[k] * Wp1[k * F + j];
    t1[j] = fmaxf(a, 0.f);
    __syncthreads();
    if (j < 32) {
        float a2 = bp2[j];
#pragma unroll
        for (int k = 0; k < F; k++) a2 += t1[k] * Wp2[k * 32 + j];
        out[g * 32 + j] = a2;
    }
}

// ---------------- launch -----------------------------------------------------

extern "C" void kernel_launch(void* const* d_in, const int* in_sizes, int n_in,
                              void* d_out, int out_size) {
    const float* x    = (const float*)d_in[0];
    const int*   ei   = (const int*)d_in[1];
    const int*   batch= (const int*)d_in[2];
    const float* W1   = (const float*)d_in[3];
    const float* b1   = (const float*)d_in[4];
    const float* W2   = (const float*)d_in[5];
    const float* b2   = (const float*)d_in[6];
    const float* W3   = (const float*)d_in[7];
    const float* b3   = (const float*)d_in[8];
    const float* Wp1  = (const float*)d_in[9];
    const float* bp1  = (const float*)d_in[10];
    const float* Wp2  = (const float*)d_in[11];
    const float* bp2  = (const float*)d_in[12];
    float* out = (float*)d_out;

    int N = in_sizes[0] / 128;
    int E = in_sizes[1] / 2;
    int G = out_size / 32;
    const int* src = ei;
    const int* dst = ei + E;

    float *p_h, *p_xb;
    cudaGetSymbolAddress((void**)&p_h, g_h);
    cudaGetSymbolAddress((void**)&p_xb, g_xb);

    const int T = 256;
    int nblk = (N + SCAN_B - 1) / SCAN_B;

    k_zero_cnt<<<(N + T - 1) / T, T>>>(N);
    k_hist<<<(E + T - 1) / T, T>>>(dst, E);
    k_scan_local<<<nblk, SCAN_B>>>(N);
    k_scan_bsum<<<1, 1>>>(nblk, N);
    k_scan_final<<<nblk, SCAN_B>>>(N);
    k_fill<<<(E + T - 1) / T, T>>>(src, dst, E);

    int gemm_blocks = (N + BM - 1) / BM;
    int agg_blocks  = (N + 7) / 8;

    // layer 1
    k_gemm_t<<<gemm_blocks, T>>>(x, W1, p_h, N, 128);
    k_agg<<<agg_blocks, T>>>(p_h, b1, p_xb, N, 1);
    // layer 2
    k_gemm_t<<<gemm_blocks, T>>>(p_xb, W2, p_h, N, 64);
    k_agg<<<agg_blocks, T>>>(p_h, b2, p_xb, N, 0);
    // layer 3
    k_gemm_t<<<gemm_blocks, T>>>(p_xb, W3, p_h, N, 64);
    k_agg<<<agg_blocks, T>>>(p_h, b3, p_xb, N, 0);

    // fused pooling + MLP
    k_poolmlp<<<G, F>>>(batch, N, Wp1, bp1, Wp2, bp2, out);
}

// round 4
// speedup vs baseline: 2.3343x; 1.0170x over previous
#include <cuda_runtime.h>
#include <cuda_fp16.h>

// ---------------------------------------------------------------------------
// GNNEncoder: 3x GCNConv(relu) -> sum of layer outputs -> global_mean_pool -> MLP
// R4: fp16 message buffer (half the gather traffic), quarter-warp-per-edge
// aggregate, single-pass decoupled scan, memset-based init.
// ---------------------------------------------------------------------------

#define NMAX 50000
#define EMAX 800000
#define GMAX 2500
#define F 64
#define SCAN_B 1024
#define NBLK_MAX ((NMAX + SCAN_B - 1) / SCAN_B + 1)

__device__ int   g_cnt[NMAX];
__device__ int   g_rowptr[NMAX + 1];
__device__ int   g_cursor[NMAX];
__device__ float g_dis[NMAX];
__device__ float g_dis2[NMAX];
__device__ int2  g_epack[EMAX];
__device__ int   g_bpub[NBLK_MAX];          // published block sums (+1), 0 = not ready
__device__ __align__(16) __half g_h16[NMAX * F];   // fp16 GEMM output (gather target)
__device__ float g_xb[NMAX * F];
__device__ float g_hsum[NMAX * F];

// ---------------- graph preprocessing ----------------

__global__ void k_hist(const int* __restrict__ dst, int E) {
    int e = blockIdx.x * blockDim.x + threadIdx.x;
    if (e < E) atomicAdd(&g_cnt[dst[e]], 1);
}

// Single-pass scan: per-block scan + publish (sum+1) + warp-parallel spin on
// predecessors. All <=49 blocks are co-resident -> no deadlock. Also computes
// dis/dis2 and writes rowptr (exclusive) + cursor.
__global__ void k_scan(int n, int nblk) {
    __shared__ int wsum[32];
    __shared__ int s_off;
    int i = blockIdx.x * SCAN_B + threadIdx.x;
    int lane = threadIdx.x & 31, wid = threadIdx.x >> 5;
    int v = (i < n) ? g_cnt[i] : 0;
    if (i < n) {
        float deg = (float)(v + 1);
        g_dis[i]  = rsqrtf(deg);
        g_dis2[i] = 1.0f / deg;
    }
    int s = v;
#pragma unroll
    for (int o = 1; o < 32; o <<= 1) {
        int t = __shfl_up_sync(0xffffffffu, s, o);
        if (lane >= o) s += t;
    }
    if (lane == 31) wsum[wid] = s;
    __syncthreads();
    if (wid == 0) {
        int ws = wsum[lane];
#pragma unroll
        for (int o = 1; o < 32; o <<= 1) {
            int t = __shfl_up_sync(0xffffffffu, ws, o);
            if (lane >= o) ws += t;
        }
        wsum[lane] = ws;
    }
    __syncthreads();
    int incl = s + (wid > 0 ? wsum[wid - 1] : 0);
    int blk_total = wsum[31];
    // publish this block's total ASAP
    if (threadIdx.x == 0) {
        volatile int* pub = (volatile int*)g_bpub;
        pub[blockIdx.x] = blk_total + 1;
    }
    // warp 0: gather predecessor offsets (spin)
    if (wid == 0) {
        int off = 0;
        volatile int* pub = (volatile int*)g_bpub;
        for (int j = lane; j < blockIdx.x; j += 32) {
            int pv;
            do { pv = pub[j]; } while (pv == 0);
            off += pv - 1;
        }
#pragma unroll
        for (int o = 16; o; o >>= 1) off += __shfl_xor_sync(0xffffffffu, off, o);
        if (lane == 0) s_off = off;
    }
    __syncthreads();
    int base = s_off;
    if (i < n) {
        int excl = base + incl - v;
        g_rowptr[i] = excl;
        g_cursor[i] = excl;
    }
    if (blockIdx.x == nblk - 1 && threadIdx.x == SCAN_B - 1)
        g_rowptr[n] = base + incl;
}

__global__ void k_fill(const int* __restrict__ src, const int* __restrict__ dst, int E) {
    int e = blockIdx.x * blockDim.x + threadIdx.x;
    if (e >= E) return;
    int s = src[e], d = dst[e];
    float nm = g_dis[s] * g_dis[d];
    int pos = atomicAdd(&g_cursor[d], 1);
    g_epack[pos] = make_int2(s, __float_as_int(nm));
}

// ---------------- GEMM: H16[n,64] = X[n,K] @ W[K,64], fp16 output ------------

#define BM 64
#define BK 16

__global__ void k_gemm_t(const float* __restrict__ X, const float* __restrict__ W,
                         __half* __restrict__ H, int n, int K) {
    __shared__ float As[BK][BM];
    __shared__ float Bs[BK][F];
    int tx = threadIdx.x & 15;
    int ty = threadIdx.x >> 4;
    int row0 = blockIdx.x * BM;

    float acc[4][4] = {};

    for (int kb = 0; kb < K; kb += BK) {
        {
            int r  = threadIdx.x >> 2;
            int c4 = (threadIdx.x & 3) * 4;
            float4 v = make_float4(0.f, 0.f, 0.f, 0.f);
            if (row0 + r < n)
                v = *(const float4*)&X[(size_t)(row0 + r) * K + kb + c4];
            As[c4 + 0][r] = v.x; As[c4 + 1][r] = v.y;
            As[c4 + 2][r] = v.z; As[c4 + 3][r] = v.w;
        }
        {
            int r = threadIdx.x >> 4;
            int c = (threadIdx.x & 15) * 4;
            *(float4*)&Bs[r][c] = *(const float4*)&W[(size_t)(kb + r) * F + c];
        }
        __syncthreads();
#pragma unroll
        for (int k = 0; k < BK; k++) {
            float4 a = *(const float4*)&As[k][ty * 4];
            float4 b = *(const float4*)&Bs[k][tx * 4];
            float av[4] = {a.x, a.y, a.z, a.w};
            float bv[4] = {b.x, b.y, b.z, b.w};
#pragma unroll
            for (int i = 0; i < 4; i++)
#pragma unroll
                for (int j = 0; j < 4; j++)
                    acc[i][j] += av[i] * bv[j];
        }
        __syncthreads();
    }
#pragma unroll
    for (int i = 0; i < 4; i++) {
        int r = row0 + ty * 4 + i;
        if (r < n) {
            __half2 p0 = __floats2half2_rn(acc[i][0], acc[i][1]);
            __half2 p1 = __floats2half2_rn(acc[i][2], acc[i][3]);
            uint2 pk;
            pk.x = *(unsigned int*)&p0;
            pk.y = *(unsigned int*)&p1;
            *(uint2*)&H[(size_t)r * F + tx * 4] = pk;
        }
    }
}

// ---------------- CSR aggregate: warp per dst, quarter-warp per edge --------
// h is fp16: 64 features = 128B/node = 8 lanes x uint4. Warp = 4 quarters,
// quarter q handles edges k+q. Lane ql (0..7) accumulates features
// [ql*8, ql*8+8) in fp32. Combine quarters via shfl_xor(8,16).

__device__ __forceinline__ void acc_edge(float* acc, const __half* __restrict__ h,
                                         int srcn, float nm, int ql) {
    uint4 u = __ldg((const uint4*)(h + (size_t)srcn * F) + ql);
    __half2* hp = (__half2*)&u;
    float2 f0 = __half22float2(hp[0]);
    float2 f1 = __half22float2(hp[1]);
    float2 f2 = __half22float2(hp[2]);
    float2 f3 = __half22float2(hp[3]);
    acc[0] += nm * f0.x; acc[1] += nm * f0.y;
    acc[2] += nm * f1.x; acc[3] += nm * f1.y;
    acc[4] += nm * f2.x; acc[5] += nm * f2.y;
    acc[6] += nm * f3.x; acc[7] += nm * f3.y;
}

__global__ void k_agg(const __half* __restrict__ h, const float* __restrict__ b,
                      float* __restrict__ xout, int n, int first) {
    int w = (blockIdx.x * blockDim.x + threadIdx.x) >> 5;
    int lane = threadIdx.x & 31;
    if (w >= n) return;
    int qid = lane >> 3;   // quarter 0..3
    int ql  = lane & 7;    // lane in quarter

    float acc[8] = {};
    int beg = g_rowptr[w], end = g_rowptr[w + 1];
    int k = beg;

    // 8 edges / warp-iteration (2 per quarter, independent loads)
    for (; k + 8 <= end; k += 8) {
        int2 e0 = g_epack[k + qid];
        int2 e1 = g_epack[k + 4 + qid];
        acc_edge(acc, h, e0.x, __int_as_float(e0.y), ql);
        acc_edge(acc, h, e1.x, __int_as_float(e1.y), ql);
    }
    if (k + 4 <= end) {
        int2 e0 = g_epack[k + qid];
        acc_edge(acc, h, e0.x, __int_as_float(e0.y), ql);
        k += 4;
    }
    if (k + qid < end) {
        int2 e0 = g_epack[k + qid];
        acc_edge(acc, h, e0.x, __int_as_float(e0.y), ql);
    }
    // combine quarters
#pragma unroll
    for (int j = 0; j < 8; j++) {
        acc[j] += __shfl_xor_sync(0xffffffffu, acc[j], 8);
        acc[j] += __shfl_xor_sync(0xffffffffu, acc[j], 16);
    }

    // self loop + bias + relu (all quarters compute; quarters 0/1 write)
    float self = g_dis2[w];
    acc_edge(acc, h, w, self, ql);   // adds self*h[w]

    float4 bv0 = __ldg((const float4*)b + ql * 2);
    float4 bv1 = __ldg((const float4*)b + ql * 2 + 1);
    float r0 = fmaxf(acc[0] + bv0.x, 0.f);
    float r1 = fmaxf(acc[1] + bv0.y, 0.f);
    float r2 = fmaxf(acc[2] + bv0.z, 0.f);
    float r3 = fmaxf(acc[3] + bv0.w, 0.f);
    float r4 = fmaxf(acc[4] + bv1.x, 0.f);
    float r5 = fmaxf(acc[5] + bv1.y, 0.f);
    float r6 = fmaxf(acc[6] + bv1.z, 0.f);
    float r7 = fmaxf(acc[7] + bv1.w, 0.f);

    size_t o4 = (size_t)w * 16 + ql * 2;
    if (qid == 0) {
        ((float4*)xout)[o4]     = make_float4(r0, r1, r2, r3);
        ((float4*)xout)[o4 + 1] = make_float4(r4, r5, r6, r7);
    } else if (qid == 1) {
        float4* hs = (float4*)g_hsum;
        if (first) {
            hs[o4]     = make_float4(r0, r1, r2, r3);
            hs[o4 + 1] = make_float4(r4, r5, r6, r7);
        } else {
            float4 a0 = hs[o4], a1 = hs[o4 + 1];
            a0.x += r0; a0.y += r1; a0.z += r2; a0.w += r3;
            a1.x += r4; a1.y += r5; a1.z += r6; a1.w += r7;
            hs[o4] = a0; hs[o4 + 1] = a1;
        }
    }
}

// ---------------- fused pool + MLP ------------------------------------------

__device__ __forceinline__ int lower_bound_i(const int* __restrict__ a, int n, int key) {
    int lo = 0, hi = n;
    while (lo < hi) {
        int mid = (lo + hi) >> 1;
        if (a[mid] < key) lo = mid + 1; else hi = mid;
    }
    return lo;
}

__global__ void k_poolmlp(const int* __restrict__ batch, int n,
                          const float* __restrict__ Wp1, const float* __restrict__ bp1,
                          const float* __restrict__ Wp2, const float* __restrict__ bp2,
                          float* __restrict__ out) {
    __shared__ int s_range[2];
    __shared__ float p[F], t1[F];
    int g = blockIdx.x, j = threadIdx.x;
    if (j < 2) s_range[j] = lower_bound_i(batch, n, g + j);
    __syncthreads();
    int st = s_range[0], en = s_range[1];
    float acc = 0.f;
    for (int node = st; node < en; node++)
        acc += g_hsum[(size_t)node * F + j];
    float inv = 1.0f / fmaxf((float)(en - st), 1.0f);
    p[j] = acc * inv;
    __syncthreads();
    float a = bp1[j];
#pragma unroll
    for (int k = 0; k < F; k++) a += p[k] * Wp1[k * F + j];
    t1[j] = fmaxf(a, 0.f);
    __syncthreads();
    if (j < 32) {
        float a2 = bp2[j];
#pragma unroll
        for (int k = 0; k < F; k++) a2 += t1[k] * Wp2[k * 32 + j];
        out[g * 32 + j] = a2;
    }
}

// ---------------- launch -----------------------------------------------------

extern "C" void kernel_launch(void* const* d_in, const int* in_sizes, int n_in,
                              void* d_out, int out_size) {
    const float* x    = (const float*)d_in[0];
    const int*   ei   = (const int*)d_in[1];
    const int*   batch= (const int*)d_in[2];
    const float* W1   = (const float*)d_in[3];
    const float* b1   = (const float*)d_in[4];
    const float* W2   = (const float*)d_in[5];
    const float* b2   = (const float*)d_in[6];
    const float* W3   = (const float*)d_in[7];
    const float* b3   = (const float*)d_in[8];
    const float* Wp1  = (const float*)d_in[9];
    const float* bp1  = (const float*)d_in[10];
    const float* Wp2  = (const float*)d_in[11];
    const float* bp2  = (const float*)d_in[12];
    float* out = (float*)d_out;

    int N = in_sizes[0] / 128;
    int E = in_sizes[1] / 2;
    int G = out_size / 32;
    const int* src = ei;
    const int* dst = ei + E;

    __half* p_h;
    float* p_xb;
    int *p_cnt, *p_pub;
    cudaGetSymbolAddress((void**)&p_h, g_h16);
    cudaGetSymbolAddress((void**)&p_xb, g_xb);
    cudaGetSymbolAddress((void**)&p_cnt, g_cnt);
    cudaGetSymbolAddress((void**)&p_pub, g_bpub);

    const int T = 256;
    int nblk = (N + SCAN_B - 1) / SCAN_B;

    cudaMemsetAsync(p_cnt, 0, (size_t)N * sizeof(int));
    cudaMemsetAsync(p_pub, 0, (size_t)nblk * sizeof(int));
    k_hist<<<(E + T - 1) / T, T>>>(dst, E);
    k_scan<<<nblk, SCAN_B>>>(N, nblk);
    k_fill<<<(E + T - 1) / T, T>>>(src, dst, E);

    int gemm_blocks = (N + BM - 1) / BM;
    int agg_blocks  = (N + 7) / 8;

    // layer 1
    k_gemm_t<<<gemm_blocks, T>>>(x, W1, p_h, N, 128);
    k_agg<<<agg_blocks, T>>>(p_h, b1, p_xb, N, 1);
    // layer 2
    k_gemm_t<<<gemm_blocks, T>>>(p_xb, W2, p_h, N, 64);
    k_agg<<<agg_blocks, T>>>(p_h, b2, p_xb, N, 0);
    // layer 3
    k_gemm_t<<<gemm_blocks, T>>>(p_xb, W3, p_h, N, 64);
    k_agg<<<agg_blocks, T>>>(p_h, b3, p_xb, N, 0);

    // fused pooling + MLP
    k_poolmlp<<<G, F>>>(batch, N, Wp1, bp1, Wp2, bp2, out);
}

// round 5
// speedup vs baseline: 2.7080x; 1.1601x over previous
#include <cuda_runtime.h>
#include <cuda_fp16.h>

// ---------------------------------------------------------------------------
// GNNEncoder: 3x GCNConv(relu) -> sum of layer outputs -> global_mean_pool -> MLP
// R5: tensor-core GEMM (mma.sync m16n8k16 fp16 -> fp32 acc), fp16 activations
// end-to-end for GEMM/gather, fp32 hsum/pool path for accuracy.
// ---------------------------------------------------------------------------

#define NMAX 50000
#define EMAX 800000
#define GMAX 2500
#define F 64
#define SCAN_B 1024
#define NBLK_MAX ((NMAX + SCAN_B - 1) / SCAN_B + 1)

__device__ int   g_cnt[NMAX];
__device__ int   g_rowptr[NMAX + 1];
__device__ int   g_cursor[NMAX];
__device__ float g_dis[NMAX];
__device__ float g_dis2[NMAX];
__device__ int2  g_epack[EMAX];
__device__ int   g_bpub[NBLK_MAX];
__device__ __align__(16) __half g_a16[NMAX * 128];   // fp16 X (layer-1 GEMM input)
__device__ __align__(16) __half g_xb16[NMAX * F];    // fp16 activations (layer 2/3 input)
__device__ __align__(16) __half g_h16[NMAX * F];     // fp16 GEMM output (gather target)
__device__ __align__(16) __half g_w16t[3][64 * 128]; // W^T fp16, k-contiguous, stride 128
__device__ float g_hsum[NMAX * F];

// ---------------- converts ----------------

__global__ void k_cvtX(const float* __restrict__ X, __half* __restrict__ A, int total4) {
    int i = blockIdx.x * blockDim.x + threadIdx.x;
    if (i >= total4) return;
    float4 v = *(const float4*)(X + (size_t)i * 4);
    __half2 h0 = __floats2half2_rn(v.x, v.y);
    __half2 h1 = __floats2half2_rn(v.z, v.w);
    uint2 u;
    u.x = *(unsigned*)&h0; u.y = *(unsigned*)&h1;
    *(uint2*)(A + (size_t)i * 4) = u;
}

// Wt[n*128 + k] = W[k*64 + n], fp16
__global__ void k_cvtW(const float* __restrict__ W, __half* __restrict__ Wt, int K) {
    int i = blockIdx.x * blockDim.x + threadIdx.x;
    if (i >= K * 64) return;
    int k = i >> 6, nn = i & 63;
    Wt[nn * 128 + k] = __float2half(W[k * 64 + nn]);
}

// ---------------- graph preprocessing ----------------

__global__ void k_hist(const int* __restrict__ dst, int E) {
    int e = blockIdx.x * blockDim.x + threadIdx.x;
    if (e < E) atomicAdd(&g_cnt[dst[e]], 1);
}

// Single-pass decoupled scan (<=49 blocks co-resident). Also dis/dis2.
__global__ void k_scan(int n, int nblk) {
    __shared__ int wsum[32];
    __shared__ int s_off;
    int i = blockIdx.x * SCAN_B + threadIdx.x;
    int lane = threadIdx.x & 31, wid = threadIdx.x >> 5;
    int v = (i < n) ? g_cnt[i] : 0;
    if (i < n) {
        float deg = (float)(v + 1);
        g_dis[i]  = rsqrtf(deg);
        g_dis2[i] = 1.0f / deg;
    }
    int s = v;
#pragma unroll
    for (int o = 1; o < 32; o <<= 1) {
        int t = __shfl_up_sync(0xffffffffu, s, o);
        if (lane >= o) s += t;
    }
    if (lane == 31) wsum[wid] = s;
    __syncthreads();
    if (wid == 0) {
        int ws = wsum[lane];
#pragma unroll
        for (int o = 1; o < 32; o <<= 1) {
            int t = __shfl_up_sync(0xffffffffu, ws, o);
            if (lane >= o) ws += t;
        }
        wsum[lane] = ws;
    }
    __syncthreads();
    int incl = s + (wid > 0 ? wsum[wid - 1] : 0);
    int blk_total = wsum[31];
    if (threadIdx.x == 0) {
        volatile int* pub = (volatile int*)g_bpub;
        pub[blockIdx.x] = blk_total + 1;
    }
    if (wid == 0) {
        int off = 0;
        volatile int* pub = (volatile int*)g_bpub;
        for (int j = lane; j < blockIdx.x; j += 32) {
            int pv;
            do { pv = pub[j]; } while (pv == 0);
            off += pv - 1;
        }
#pragma unroll
        for (int o = 16; o; o >>= 1) off += __shfl_xor_sync(0xffffffffu, off, o);
        if (lane == 0) s_off = off;
    }
    __syncthreads();
    int base = s_off;
    if (i < n) {
        int excl = base + incl - v;
        g_rowptr[i] = excl;
        g_cursor[i] = excl;
    }
    if (blockIdx.x == nblk - 1 && threadIdx.x == SCAN_B - 1)
        g_rowptr[n] = base + incl;
}

__global__ void k_fill(const int* __restrict__ src, const int* __restrict__ dst, int E) {
    int e = blockIdx.x * blockDim.x + threadIdx.x;
    if (e >= E) return;
    int s = src[e], d = dst[e];
    float nm = g_dis[s] * g_dis[d];
    int pos = atomicAdd(&g_cursor[d], 1);
    g_epack[pos] = make_int2(s, __float_as_int(nm));
}

// ---------------- tensor-core GEMM: H16[n,64] = A16[n,K] @ W[K,64] ----------
// Block: 256 thr = 8 warps, tile BM=128 x BN=64, BK=32. Warp tile 32x32 =
// 2(m) x 4(n) mma.m16n8k16, 2 k-subtiles per BK. Fragments via LDS.b32
// (A row-major; W transposed so B k-pairs contiguous). 80B smem row stride.

#define GBM 128
#define GBK 32
#define APAD 40   // halves per smem row (80B, conflict-free)

__global__ void k_gemm_mma(const __half* __restrict__ A, const __half* __restrict__ Wt,
                           __half* __restrict__ H, int n, int K) {
    __shared__ __half As[GBM * APAD];
    __shared__ __half Bs[64 * APAD];
    int row0 = blockIdx.x * GBM;
    int tid = threadIdx.x, lane = tid & 31, warp = tid >> 5;
    int wm = (warp >> 1) * 32, wn = (warp & 1) * 32;
    int g = lane >> 2, t = lane & 3;

    float d[2][4][4] = {};

    for (int kb = 0; kb < K; kb += GBK) {
        // A tile: 128 rows x 32 halves (512 uint4, 2 per thread)
#pragma unroll
        for (int it = 0; it < 2; it++) {
            int idx = tid + it * 256;
            int r = idx >> 2, seg = idx & 3;
            uint4 v = make_uint4(0u, 0u, 0u, 0u);
            if (row0 + r < n)
                v = *(const uint4*)(A + (size_t)(row0 + r) * K + kb + seg * 8);
            *(uint4*)(As + r * APAD + seg * 8) = v;
        }
        // B tile: 64 rows (n) x 32 halves (k), Wt stride 128
        {
            int r = tid >> 2, seg = tid & 3;
            uint4 v = *(const uint4*)(Wt + (size_t)r * 128 + kb + seg * 8);
            *(uint4*)(Bs + r * APAD + seg * 8) = v;
        }
        __syncthreads();
#pragma unroll
        for (int kk = 0; kk < 2; kk++) {
            unsigned a[2][4], b[4][2];
#pragma unroll
            for (int i = 0; i < 2; i++) {
                const __half* ap = As + (wm + i * 16 + g) * APAD + kk * 16 + t * 2;
                a[i][0] = *(const unsigned*)ap;
                a[i][1] = *(const unsigned*)(ap + 8 * APAD);
                a[i][2] = *(const unsigned*)(ap + 8);
                a[i][3] = *(const unsigned*)(ap + 8 * APAD + 8);
            }
#pragma unroll
            for (int j = 0; j < 4; j++) {
                const __half* bp = Bs + (wn + j * 8 + g) * APAD + kk * 16 + t * 2;
                b[j][0] = *(const unsigned*)bp;
                b[j][1] = *(const unsigned*)(bp + 8);
            }
#pragma unroll
            for (int i = 0; i < 2; i++)
#pragma unroll
                for (int j = 0; j < 4; j++)
                    asm volatile(
                        "mma.sync.aligned.m16n8k16.row.col.f32.f16.f16.f32 "
                        "{%0,%1,%2,%3}, {%4,%5,%6,%7}, {%8,%9}, {%0,%1,%2,%3};"
                        : "+f"(d[i][j][0]), "+f"(d[i][j][1]),
                          "+f"(d[i][j][2]), "+f"(d[i][j][3])
                        : "r"(a[i][0]), "r"(a[i][1]), "r"(a[i][2]), "r"(a[i][3]),
                          "r"(b[j][0]), "r"(b[j][1]));
        }
        __syncthreads();
    }
#pragma unroll
    for (int i = 0; i < 2; i++) {
        int r0 = row0 + wm + i * 16 + g;
#pragma unroll
        for (int j = 0; j < 4; j++) {
            int c = wn + j * 8 + t * 2;
            __half2 lo = __floats2half2_rn(d[i][j][0], d[i][j][1]);
            __half2 hi = __floats2half2_rn(d[i][j][2], d[i][j][3]);
            if (r0 < n)     *(__half2*)(H + (size_t)r0 * F + c) = lo;
            if (r0 + 8 < n) *(__half2*)(H + (size_t)(r0 + 8) * F + c) = hi;
        }
    }
}

// ---------------- CSR aggregate: warp per dst, quarter-warp per edge --------

__device__ __forceinline__ void acc_edge(float* acc, const __half* __restrict__ h,
                                         int srcn, float nm, int ql) {
    uint4 u = __ldg((const uint4*)(h + (size_t)srcn * F) + ql);
    __half2* hp = (__half2*)&u;
    float2 f0 = __half22float2(hp[0]);
    float2 f1 = __half22float2(hp[1]);
    float2 f2 = __half22float2(hp[2]);
    float2 f3 = __half22float2(hp[3]);
    acc[0] += nm * f0.x; acc[1] += nm * f0.y;
    acc[2] += nm * f1.x; acc[3] += nm * f1.y;
    acc[4] += nm * f2.x; acc[5] += nm * f2.y;
    acc[6] += nm * f3.x; acc[7] += nm * f3.y;
}

__global__ void k_agg(const __half* __restrict__ h, const float* __restrict__ b,
                      __half* __restrict__ xout, int n, int first) {
    int w = (blockIdx.x * blockDim.x + threadIdx.x) >> 5;
    int lane = threadIdx.x & 31;
    if (w >= n) return;
    int qid = lane >> 3;
    int ql  = lane & 7;

    float acc[8] = {};
    int beg = g_rowptr[w], end = g_rowptr[w + 1];
    int k = beg;

    for (; k + 8 <= end; k += 8) {
        int2 e0 = g_epack[k + qid];
        int2 e1 = g_epack[k + 4 + qid];
        acc_edge(acc, h, e0.x, __int_as_float(e0.y), ql);
        acc_edge(acc, h, e1.x, __int_as_float(e1.y), ql);
    }
    if (k + 4 <= end) {
        int2 e0 = g_epack[k + qid];
        acc_edge(acc, h, e0.x, __int_as_float(e0.y), ql);
        k += 4;
    }
    if (k + qid < end) {
        int2 e0 = g_epack[k + qid];
        acc_edge(acc, h, e0.x, __int_as_float(e0.y), ql);
    }
#pragma unroll
    for (int j = 0; j < 8; j++) {
        acc[j] += __shfl_xor_sync(0xffffffffu, acc[j], 8);
        acc[j] += __shfl_xor_sync(0xffffffffu, acc[j], 16);
    }

    float self = g_dis2[w];
    acc_edge(acc, h, w, self, ql);   // self loop

    float4 bv0 = __ldg((const float4*)b + ql * 2);
    float4 bv1 = __ldg((const float4*)b + ql * 2 + 1);
    float r0 = fmaxf(acc[0] + bv0.x, 0.f);
    float r1 = fmaxf(acc[1] + bv0.y, 0.f);
    float r2 = fmaxf(acc[2] + bv0.z, 0.f);
    float r3 = fmaxf(acc[3] + bv0.w, 0.f);
    float r4 = fmaxf(acc[4] + bv1.x, 0.f);
    float r5 = fmaxf(acc[5] + bv1.y, 0.f);
    float r6 = fmaxf(acc[6] + bv1.z, 0.f);
    float r7 = fmaxf(acc[7] + bv1.w, 0.f);

    if (qid == 0) {
        // fp16 activation for next GEMM
        __half2 q0 = __floats2half2_rn(r0, r1);
        __half2 q1 = __floats2half2_rn(r2, r3);
        __half2 q2 = __floats2half2_rn(r4, r5);
        __half2 q3 = __floats2half2_rn(r6, r7);
        uint4 u;
        u.x = *(unsigned*)&q0; u.y = *(unsigned*)&q1;
        u.z = *(unsigned*)&q2; u.w = *(unsigned*)&q3;
        *(uint4*)(xout + (size_t)w * F + ql * 8) = u;
    } else if (qid == 1) {
        size_t o4 = (size_t)w * 16 + ql * 2;
        float4* hs = (float4*)g_hsum;
        if (first) {
            hs[o4]     = make_float4(r0, r1, r2, r3);
            hs[o4 + 1] = make_float4(r4, r5, r6, r7);
        } else {
            float4 a0 = hs[o4], a1 = hs[o4 + 1];
            a0.x += r0; a0.y += r1; a0.z += r2; a0.w += r3;
            a1.x += r4; a1.y += r5; a1.z += r6; a1.w += r7;
            hs[o4] = a0; hs[o4 + 1] = a1;
        }
    }
}

// ---------------- fused pool + MLP ------------------------------------------

__device__ __forceinline__ int lower_bound_i(const int* __restrict__ a, int n, int key) {
    int lo = 0, hi = n;
    while (lo < hi) {
        int mid = (lo + hi) >> 1;
        if (a[mid] < key) lo = mid + 1; else hi = mid;
    }
    return lo;
}

__global__ void k_poolmlp(const int* __restrict__ batch, int n,
                          const float* __restrict__ Wp1, const float* __restrict__ bp1,
                          const float* __restrict__ Wp2, const float* __restrict__ bp2,
                          float* __restrict__ out) {
    __shared__ int s_range[2];
    __shared__ float p[F], t1[F];
    int g = blockIdx.x, j = threadIdx.x;
    if (j < 2) s_range[j] = lower_bound_i(batch, n, g + j);
    __syncthreads();
    int st = s_range[0], en = s_range[1];
    float acc = 0.f;
    for (int node = st; node < en; node++)
        acc += g_hsum[(size_t)node * F + j];
    float inv = 1.0f / fmaxf((float)(en - st), 1.0f);
    p[j] = acc * inv;
    __syncthreads();
    float a = bp1[j];
#pragma unroll
    for (int k = 0; k < F; k++) a += p[k] * Wp1[k * F + j];
    t1[j] = fmaxf(a, 0.f);
    __syncthreads();
    if (j < 32) {
        float a2 = bp2[j];
#pragma unroll
        for (int k = 0; k < F; k++) a2 += t1[k] * Wp2[k * 32 + j];
        out[g * 32 + j] = a2;
    }
}

// ---------------- launch -----------------------------------------------------

extern "C" void kernel_launch(void* const* d_in, const int* in_sizes, int n_in,
                              void* d_out, int out_size) {
    const float* x    = (const float*)d_in[0];
    const int*   ei   = (const int*)d_in[1];
    const int*   batch= (const int*)d_in[2];
    const float* W1   = (const float*)d_in[3];
    const float* b1   = (const float*)d_in[4];
    const float* W2   = (const float*)d_in[5];
    const float* b2   = (const float*)d_in[6];
    const float* W3   = (const float*)d_in[7];
    const float* b3   = (const float*)d_in[8];
    const float* Wp1  = (const float*)d_in[9];
    const float* bp1  = (const float*)d_in[10];
    const float* Wp2  = (const float*)d_in[11];
    const float* bp2  = (const float*)d_in[12];
    float* out = (float*)d_out;

    int N = in_sizes[0] / 128;
    int E = in_sizes[1] / 2;
    int G = out_size / 32;
    const int* src = ei;
    const int* dst = ei + E;

    __half *p_a16, *p_xb16, *p_h, *p_wt;
    int *p_cnt, *p_pub;
    cudaGetSymbolAddress((void**)&p_a16, g_a16);
    cudaGetSymbolAddress((void**)&p_xb16, g_xb16);
    cudaGetSymbolAddress((void**)&p_h, g_h16);
    cudaGetSymbolAddress((void**)&p_wt, g_w16t);
    cudaGetSymbolAddress((void**)&p_cnt, g_cnt);
    cudaGetSymbolAddress((void**)&p_pub, g_bpub);

    __half* wt1 = p_wt;
    __half* wt2 = p_wt + 64 * 128;
    __half* wt3 = p_wt + 2 * 64 * 128;

    const int T = 256;
    int nblk = (N + SCAN_B - 1) / SCAN_B;

    cudaMemsetAsync(p_cnt, 0, (size_t)N * sizeof(int));
    cudaMemsetAsync(p_pub, 0, (size_t)nblk * sizeof(int));

    // converts (independent of graph preprocessing)
    int total4 = N * 128 / 4;
    k_cvtX<<<(total4 + T - 1) / T, T>>>(x, p_a16, total4);
    k_cvtW<<<(128 * 64 + T - 1) / T, T>>>(W1, wt1, 128);
    k_cvtW<<<(64 * 64 + T - 1) / T, T>>>(W2, wt2, 64);
    k_cvtW<<<(64 * 64 + T - 1) / T, T>>>(W3, wt3, 64);

    // graph preprocessing
    k_hist<<<(E + T - 1) / T, T>>>(dst, E);
    k_scan<<<nblk, SCAN_B>>>(N, nblk);
    k_fill<<<(E + T - 1) / T, T>>>(src, dst, E);

    int gemm_blocks = (N + GBM - 1) / GBM;
    int agg_blocks  = (N + 7) / 8;

    // layer 1
    k_gemm_mma<<<gemm_blocks, T>>>(p_a16, wt1, p_h, N, 128);
    k_agg<<<agg_blocks, T>>>(p_h, b1, p_xb16, N, 1);
    // layer 2
    k_gemm_mma<<<gemm_blocks, T>>>(p_xb16, wt2, p_h, N, 64);
    k_agg<<<agg_blocks, T>>>(p_h, b2, p_xb16, N, 0);
    // layer 3
    k_gemm_mma<<<gemm_blocks, T>>>(p_xb16, wt3, p_h, N, 64);
    k_agg<<<agg_blocks, T>>>(p_h, b3, p_xb16, N, 0);

    // fused pooling + MLP
    k_poolmlp<<<G, F>>>(batch, N, Wp1, bp1, Wp2, bp2, out);
}

// round 6
// speedup vs baseline: 2.7940x; 1.0318x over previous
#include <cuda_runtime.h>
#include <cuda_fp16.h>

// ---------------------------------------------------------------------------
// GNNEncoder: 3x GCNConv(relu) -> sum -> global_mean_pool -> MLP
// R6: fused prep kernel (cvtX + 3x cvtW + hist in one launch), single memset,
// aggregate with 16 edges/warp-iteration (4 gathers in flight per lane).
// ---------------------------------------------------------------------------

#define NMAX 50000
#define EMAX 800000
#define GMAX 2500
#define F 64
#define SCAN_B 1024
#define NBLK_MAX ((NMAX + SCAN_B - 1) / SCAN_B + 1)

__device__ int   g_cntpub[NMAX + NBLK_MAX];   // [0,N): cnt  [N,N+nblk): bpub
__device__ int   g_rowptr[NMAX + 1];
__device__ int   g_cursor[NMAX];
__device__ float g_dis[NMAX];
__device__ float g_dis2[NMAX];
__device__ int2  g_epack[EMAX];
__device__ __align__(16) __half g_a16[NMAX * 128];
__device__ __align__(16) __half g_xb16[NMAX * F];
__device__ __align__(16) __half g_h16[NMAX * F];
__device__ __align__(16) __half g_w16t[3][64 * 128]; // W^T fp16, k-contig, stride 128
__device__ float g_hsum[NMAX * F];

// ---------------- fused prep: cvtX | cvtW x3 | hist --------------------------
// block ranges: [0,nX) cvtX, [nX,nX+64) cvtW, [nX+64, nX+64+nH) hist

__global__ void k_prep(const float* __restrict__ X,
                       const float* __restrict__ W1, const float* __restrict__ W2,
                       const float* __restrict__ W3,
                       const int* __restrict__ dst,
                       int nX, int E, int total4) {
    int blk = blockIdx.x;
    if (blk < nX) {
        int i = blk * 256 + threadIdx.x;
        if (i >= total4) return;
        float4 v = *(const float4*)(X + (size_t)i * 4);
        __half2 h0 = __floats2half2_rn(v.x, v.y);
        __half2 h1 = __floats2half2_rn(v.z, v.w);
        uint2 u;
        u.x = *(unsigned*)&h0; u.y = *(unsigned*)&h1;
        *(uint2*)(g_a16 + (size_t)i * 4) = u;
        return;
    }
    blk -= nX;
    if (blk < 64) {
        int i = blk * 256 + threadIdx.x;   // 0..16383
        const float* W; __half* Wt; int idx;
        if (i < 8192)       { W = W1; Wt = g_w16t[0]; idx = i; }
        else if (i < 12288) { W = W2; Wt = g_w16t[1]; idx = i - 8192; }
        else                { W = W3; Wt = g_w16t[2]; idx = i - 12288; }
        int k = idx >> 6, nn = idx & 63;
        Wt[nn * 128 + k] = __float2half(W[k * 64 + nn]);
        return;
    }
    blk -= 64;
    int e = blk * 256 + threadIdx.x;
    if (e < E) atomicAdd(&g_cntpub[dst[e]], 1);
}

// ---------------- single-pass decoupled scan (also dis/dis2) -----------------

__global__ void k_scan(int n, int nblk) {
    __shared__ int wsum[32];
    __shared__ int s_off;
    int i = blockIdx.x * SCAN_B + threadIdx.x;
    int lane = threadIdx.x & 31, wid = threadIdx.x >> 5;
    int v = (i < n) ? g_cntpub[i] : 0;
    if (i < n) {
        float deg = (float)(v + 1);
        g_dis[i]  = rsqrtf(deg);
        g_dis2[i] = 1.0f / deg;
    }
    int s = v;
#pragma unroll
    for (int o = 1; o < 32; o <<= 1) {
        int t = __shfl_up_sync(0xffffffffu, s, o);
        if (lane >= o) s += t;
    }
    if (lane == 31) wsum[wid] = s;
    __syncthreads();
    if (wid == 0) {
        int ws = wsum[lane];
#pragma unroll
        for (int o = 1; o < 32; o <<= 1) {
            int t = __shfl_up_sync(0xffffffffu, ws, o);
            if (lane >= o) ws += t;
        }
        wsum[lane] = ws;
    }
    __syncthreads();
    int incl = s + (wid > 0 ? wsum[wid - 1] : 0);
    int blk_total = wsum[31];
    volatile int* pub = (volatile int*)(g_cntpub + n);
    if (threadIdx.x == 0) pub[blockIdx.x] = blk_total + 1;
    if (wid == 0) {
        int off = 0;
        for (int j = lane; j < blockIdx.x; j += 32) {
            int pv;
            do { pv = pub[j]; } while (pv == 0);
            off += pv - 1;
        }
#pragma unroll
        for (int o = 16; o; o >>= 1) off += __shfl_xor_sync(0xffffffffu, off, o);
        if (lane == 0) s_off = off;
    }
    __syncthreads();
    int base = s_off;
    if (i < n) {
        int excl = base + incl - v;
        g_rowptr[i] = excl;
        g_cursor[i] = excl;
    }
    if (blockIdx.x == nblk - 1 && threadIdx.x == SCAN_B - 1)
        g_rowptr[n] = base + incl;
}

__global__ void k_fill(const int* __restrict__ src, const int* __restrict__ dst, int E) {
    int e = blockIdx.x * blockDim.x + threadIdx.x;
    if (e >= E) return;
    int s = src[e], d = dst[e];
    float nm = g_dis[s] * g_dis[d];
    int pos = atomicAdd(&g_cursor[d], 1);
    g_epack[pos] = make_int2(s, __float_as_int(nm));
}

// ---------------- tensor-core GEMM: H16[n,64] = A16[n,K] @ W[K,64] ----------

#define GBM 128
#define GBK 32
#define APAD 40

__global__ void k_gemm_mma(const __half* __restrict__ A, const __half* __restrict__ Wt,
                           __half* __restrict__ H, int n, int K) {
    __shared__ __half As[GBM * APAD];
    __shared__ __half Bs[64 * APAD];
    int row0 = blockIdx.x * GBM;
    int tid = threadIdx.x, lane = tid & 31, warp = tid >> 5;
    int wm = (warp >> 1) * 32, wn = (warp & 1) * 32;
    int g = lane >> 2, t = lane & 3;

    float d[2][4][4] = {};

    for (int kb = 0; kb < K; kb += GBK) {
#pragma unroll
        for (int it = 0; it < 2; it++) {
            int idx = tid + it * 256;
            int r = idx >> 2, seg = idx & 3;
            uint4 v = make_uint4(0u, 0u, 0u, 0u);
            if (row0 + r < n)
                v = *(const uint4*)(A + (size_t)(row0 + r) * K + kb + seg * 8);
            *(uint4*)(As + r * APAD + seg * 8) = v;
        }
        {
            int r = tid >> 2, seg = tid & 3;
            uint4 v = *(const uint4*)(Wt + (size_t)r * 128 + kb + seg * 8);
            *(uint4*)(Bs + r * APAD + seg * 8) = v;
        }
        __syncthreads();
#pragma unroll
        for (int kk = 0; kk < 2; kk++) {
            unsigned a[2][4], b[4][2];
#pragma unroll
            for (int i = 0; i < 2; i++) {
                const __half* ap = As + (wm + i * 16 + g) * APAD + kk * 16 + t * 2;
                a[i][0] = *(const unsigned*)ap;
                a[i][1] = *(const unsigned*)(ap + 8 * APAD);
                a[i][2] = *(const unsigned*)(ap + 8);
                a[i][3] = *(const unsigned*)(ap + 8 * APAD + 8);
            }
#pragma unroll
            for (int j = 0; j < 4; j++) {
                const __half* bp = Bs + (wn + j * 8 + g) * APAD + kk * 16 + t * 2;
                b[j][0] = *(const unsigned*)bp;
                b[j][1] = *(const unsigned*)(bp + 8);
            }
#pragma unroll
            for (int i = 0; i < 2; i++)
#pragma unroll
                for (int j = 0; j < 4; j++)
                    asm volatile(
                        "mma.sync.aligned.m16n8k16.row.col.f32.f16.f16.f32 "
                        "{%0,%1,%2,%3}, {%4,%5,%6,%7}, {%8,%9}, {%0,%1,%2,%3};"
                        : "+f"(d[i][j][0]), "+f"(d[i][j][1]),
                          "+f"(d[i][j][2]), "+f"(d[i][j][3])
                        : "r"(a[i][0]), "r"(a[i][1]), "r"(a[i][2]), "r"(a[i][3]),
                          "r"(b[j][0]), "r"(b[j][1]));
        }
        __syncthreads();
    }
#pragma unroll
    for (int i = 0; i < 2; i++) {
        int r0 = row0 + wm + i * 16 + g;
#pragma unroll
        for (int j = 0; j < 4; j++) {
            int c = wn + j * 8 + t * 2;
            __half2 lo = __floats2half2_rn(d[i][j][0], d[i][j][1]);
            __half2 hi = __floats2half2_rn(d[i][j][2], d[i][j][3]);
            if (r0 < n)     *(__half2*)(H + (size_t)r0 * F + c) = lo;
            if (r0 + 8 < n) *(__half2*)(H + (size_t)(r0 + 8) * F + c) = hi;
        }
    }
}

// ---------------- CSR aggregate: warp per dst, quarter-warp per edge --------
// 16 edges per warp-iteration: 4 independent uint4 gathers in flight per lane.

__device__ __forceinline__ void fma8(float* acc, uint4 u, float nm) {
    __half2* hp = (__half2*)&u;
    float2 f0 = __half22float2(hp[0]);
    float2 f1 = __half22float2(hp[1]);
    float2 f2 = __half22float2(hp[2]);
    float2 f3 = __half22float2(hp[3]);
    acc[0] += nm * f0.x; acc[1] += nm * f0.y;
    acc[2] += nm * f1.x; acc[3] += nm * f1.y;
    acc[4] += nm * f2.x; acc[5] += nm * f2.y;
    acc[6] += nm * f3.x; acc[7] += nm * f3.y;
}

__global__ void k_agg(const __half* __restrict__ h, const float* __restrict__ b,
                      __half* __restrict__ xout, int n, int first) {
    int w = (blockIdx.x * blockDim.x + threadIdx.x) >> 5;
    int lane = threadIdx.x & 31;
    if (w >= n) return;
    int qid = lane >> 3;
    int ql  = lane & 7;

    int beg = g_rowptr[w], end = g_rowptr[w + 1];
    float self = g_dis2[w];

    // self-loop gather issued first (overlaps with edge loop)
    uint4 selfu = __ldg((const uint4*)(h + (size_t)w * F) + ql);

    float acc[8] = {};
    int k = beg;

    for (; k + 16 <= end; k += 16) {
        int2 e0 = g_epack[k + qid];
        int2 e1 = g_epack[k + 4 + qid];
        int2 e2 = g_epack[k + 8 + qid];
        int2 e3 = g_epack[k + 12 + qid];
        uint4 v0 = __ldg((const uint4*)(h + (size_t)e0.x * F) + ql);
        uint4 v1 = __ldg((const uint4*)(h + (size_t)e1.x * F) + ql);
        uint4 v2 = __ldg((const uint4*)(h + (size_t)e2.x * F) + ql);
        uint4 v3 = __ldg((const uint4*)(h + (size_t)e3.x * F) + ql);
        fma8(acc, v0, __int_as_float(e0.y));
        fma8(acc, v1, __int_as_float(e1.y));
        fma8(acc, v2, __int_as_float(e2.y));
        fma8(acc, v3, __int_as_float(e3.y));
    }
    if (k + 8 <= end) {
        int2 e0 = g_epack[k + qid];
        int2 e1 = g_epack[k + 4 + qid];
        uint4 v0 = __ldg((const uint4*)(h + (size_t)e0.x * F) + ql);
        uint4 v1 = __ldg((const uint4*)(h + (size_t)e1.x * F) + ql);
        fma8(acc, v0, __int_as_float(e0.y));
        fma8(acc, v1, __int_as_float(e1.y));
        k += 8;
    }
    if (k + 4 <= end) {
        int2 e0 = g_epack[k + qid];
        uint4 v0 = __ldg((const uint4*)(h + (size_t)e0.x * F) + ql);
        fma8(acc, v0, __int_as_float(e0.y));
        k += 4;
    }
    if (k + qid < end) {
        int2 e0 = g_epack[k + qid];
        uint4 v0 = __ldg((const uint4*)(h + (size_t)e0.x * F) + ql);
        fma8(acc, v0, __int_as_float(e0.y));
    }
#pragma unroll
    for (int j = 0; j < 8; j++) {
        acc[j] += __shfl_xor_sync(0xffffffffu, acc[j], 8);
        acc[j] += __shfl_xor_sync(0xffffffffu, acc[j], 16);
    }

    fma8(acc, selfu, self);   // self loop

    float4 bv0 = __ldg((const float4*)b + ql * 2);
    float4 bv1 = __ldg((const float4*)b + ql * 2 + 1);
    float r0 = fmaxf(acc[0] + bv0.x, 0.f);
    float r1 = fmaxf(acc[1] + bv0.y, 0.f);
    float r2 = fmaxf(acc[2] + bv0.z, 0.f);
    float r3 = fmaxf(acc[3] + bv0.w, 0.f);
    float r4 = fmaxf(acc[4] + bv1.x, 0.f);
    float r5 = fmaxf(acc[5] + bv1.y, 0.f);
    float r6 = fmaxf(acc[6] + bv1.z, 0.f);
    float r7 = fmaxf(acc[7] + bv1.w, 0.f);

    if (qid == 0) {
        __half2 q0 = __floats2half2_rn(r0, r1);
        __half2 q1 = __floats2half2_rn(r2, r3);
        __half2 q2 = __floats2half2_rn(r4, r5);
        __half2 q3 = __floats2half2_rn(r6, r7);
        uint4 u;
        u.x = *(unsigned*)&q0; u.y = *(unsigned*)&q1;
        u.z = *(unsigned*)&q2; u.w = *(unsigned*)&q3;
        *(uint4*)(xout + (size_t)w * F + ql * 8) = u;
    } else if (qid == 1) {
        size_t o4 = (size_t)w * 16 + ql * 2;
        float4* hs = (float4*)g_hsum;
        if (first) {
            hs[o4]     = make_float4(r0, r1, r2, r3);
            hs[o4 + 1] = make_float4(r4, r5, r6, r7);
        } else {
            float4 a0 = hs[o4], a1 = hs[o4 + 1];
            a0.x += r0; a0.y += r1; a0.z += r2; a0.w += r3;
            a1.x += r4; a1.y += r5; a1.z += r6; a1.w += r7;
            hs[o4] = a0; hs[o4 + 1] = a1;
        }
    }
}

// ---------------- fused pool + MLP ------------------------------------------

__device__ __forceinline__ int lower_bound_i(const int* __restrict__ a, int n, int key) {
    int lo = 0, hi = n;
    while (lo < hi) {
        int mid = (lo + hi) >> 1;
        if (a[mid] < key) lo = mid + 1; else hi = mid;
    }
    return lo;
}

__global__ void k_poolmlp(const int* __restrict__ batch, int n,
                          const float* __restrict__ Wp1, const float* __restrict__ bp1,
                          const float* __restrict__ Wp2, const float* __restrict__ bp2,
                          float* __restrict__ out) {
    __shared__ int s_range[2];
    __shared__ float p[F], t1[F];
    int g = blockIdx.x, j = threadIdx.x;
    if (j < 2) s_range[j] = lower_bound_i(batch, n, g + j);
    __syncthreads();
    int st = s_range[0], en = s_range[1];
    float acc = 0.f;
    for (int node = st; node < en; node++)
        acc += g_hsum[(size_t)node * F + j];
    float inv = 1.0f / fmaxf((float)(en - st), 1.0f);
    p[j] = acc * inv;
    __syncthreads();
    float a = bp1[j];
#pragma unroll
    for (int k = 0; k < F; k++) a += p[k] * Wp1[k * F + j];
    t1[j] = fmaxf(a, 0.f);
    __syncthreads();
    if (j < 32) {
        float a2 = bp2[j];
#pragma unroll
        for (int k = 0; k < F; k++) a2 += t1[k] * Wp2[k * 32 + j];
        out[g * 32 + j] = a2;
    }
}

// ---------------- launch -----------------------------------------------------

extern "C" void kernel_launch(void* const* d_in, const int* in_sizes, int n_in,
                              void* d_out, int out_size) {
    const float* x    = (const float*)d_in[0];
    const int*   ei   = (const int*)d_in[1];
    const int*   batch= (const int*)d_in[2];
    const float* W1   = (const float*)d_in[3];
    const float* b1   = (const float*)d_in[4];
    const float* W2   = (const float*)d_in[5];
    const float* b2   = (const float*)d_in[6];
    const float* W3   = (const float*)d_in[7];
    const float* b3   = (const float*)d_in[8];
    const float* Wp1  = (const float*)d_in[9];
    const float* bp1  = (const float*)d_in[10];
    const float* Wp2  = (const float*)d_in[11];
    const float* bp2  = (const float*)d_in[12];
    float* out = (float*)d_out;

    int N = in_sizes[0] / 128;
    int E = in_sizes[1] / 2;
    int G = out_size / 32;
    const int* src = ei;
    const int* dst = ei + E;

    __half *p_a16, *p_xb16, *p_h, *p_wt;
    int *p_cnt;
    cudaGetSymbolAddress((void**)&p_a16, g_a16);
    cudaGetSymbolAddress((void**)&p_xb16, g_xb16);
    cudaGetSymbolAddress((void**)&p_h, g_h16);
    cudaGetSymbolAddress((void**)&p_wt, g_w16t);
    cudaGetSymbolAddress((void**)&p_cnt, g_cntpub);

    __half* wt1 = p_wt;
    __half* wt2 = p_wt + 64 * 128;
    __half* wt3 = p_wt + 2 * 64 * 128;

    const int T = 256;
    int nblk = (N + SCAN_B - 1) / SCAN_B;

    // single memset zeroes cnt + bpub (adjacent)
    cudaMemsetAsync(p_cnt, 0, ((size_t)N + nblk) * sizeof(int));

    int total4 = N * 128 / 4;
    int nX = (total4 + T - 1) / T;
    int nH = (E + T - 1) / T;
    k_prep<<<nX + 64 + nH, T>>>(x, W1, W2, W3, dst, nX, E, total4);
    k_scan<<<nblk, SCAN_B>>>(N, nblk);
    k_fill<<<(E + T - 1) / T, T>>>(src, dst, E);

    int gemm_blocks = (N + GBM - 1) / GBM;
    int agg_blocks  = (N + 7) / 8;

    // layer 1
    k_gemm_mma<<<gemm_blocks, T>>>(p_a16, wt1, p_h, N, 128);
    k_agg<<<agg_blocks, T>>>(p_h, b1, p_xb16, N, 1);
    // layer 2
    k_gemm_mma<<<gemm_blocks, T>>>(p_xb16, wt2, p_h, N, 64);
    k_agg<<<agg_blocks, T>>>(p_h, b2, p_xb16, N, 0);
    // layer 3
    k_gemm_mma<<<gemm_blocks, T>>>(p_xb16, wt3, p_h, N, 64);
    k_agg<<<agg_blocks, T>>>(p_h, b3, p_xb16, N, 0);

    // fused pooling + MLP
    k_poolmlp<<<G, F>>>(batch, N, Wp1, bp1, Wp2, bp2, out);
}

// round 7
// speedup vs baseline: 3.2181x; 1.1518x over previous
#include <cuda_runtime.h>
#include <cuda_fp16.h>

// ---------------------------------------------------------------------------
// GNNEncoder: 3x GCNConv(relu) -> sum -> global_mean_pool -> MLP
// R7: single-shot smem GEMM (BK=64, 1 sync/chunk, fp32 convert fused into
// layer-1 tile load), hsum dropped (3 fp16 activation buffers, pool sums all).
// ---------------------------------------------------------------------------

#define NMAX 50000
#define EMAX 800000
#define GMAX 2500
#define F 64
#define SCAN_B 1024
#define NBLK_MAX ((NMAX + SCAN_B - 1) / SCAN_B + 1)

__device__ int   g_cntpub[NMAX + NBLK_MAX];   // [0,N): cnt  [N,N+nblk): bpub
__device__ int   g_rowptr[NMAX + 1];
__device__ int   g_cursor[NMAX];
__device__ float g_dis[NMAX];
__device__ float g_dis2[NMAX];
__device__ int2  g_epack[EMAX];
__device__ __align__(16) __half g_h16[NMAX * F];     // GEMM output (gather target)
__device__ __align__(16) __half g_x1[NMAX * F];      // layer activations
__device__ __align__(16) __half g_x2[NMAX * F];
__device__ __align__(16) __half g_x3[NMAX * F];
__device__ __align__(16) __half g_w16t[3][64 * 128]; // W^T fp16, k-contig, stride 128

// ---------------- fused prep: cvtW x3 | hist ---------------------------------
// block ranges: [0,64) cvtW, [64, 64+nH) hist

__global__ void k_prep(const float* __restrict__ W1, const float* __restrict__ W2,
                       const float* __restrict__ W3,
                       const int* __restrict__ dst, int E) {
    int blk = blockIdx.x;
    if (blk < 64) {
        int i = blk * 256 + threadIdx.x;   // 0..16383
        const float* W; __half* Wt; int idx;
        if (i < 8192)       { W = W1; Wt = g_w16t[0]; idx = i; }
        else if (i < 12288) { W = W2; Wt = g_w16t[1]; idx = i - 8192; }
        else                { W = W3; Wt = g_w16t[2]; idx = i - 12288; }
        int k = idx >> 6, nn = idx & 63;
        Wt[nn * 128 + k] = __float2half(W[k * 64 + nn]);
        return;
    }
    blk -= 64;
    int e = blk * 256 + threadIdx.x;
    if (e < E) atomicAdd(&g_cntpub[dst[e]], 1);
}

// ---------------- single-pass decoupled scan (also dis/dis2) -----------------

__global__ void k_scan(int n, int nblk) {
    __shared__ int wsum[32];
    __shared__ int s_off;
    int i = blockIdx.x * SCAN_B + threadIdx.x;
    int lane = threadIdx.x & 31, wid = threadIdx.x >> 5;
    int v = (i < n) ? g_cntpub[i] : 0;
    if (i < n) {
        float deg = (float)(v + 1);
        g_dis[i]  = rsqrtf(deg);
        g_dis2[i] = 1.0f / deg;
    }
    int s = v;
#pragma unroll
    for (int o = 1; o < 32; o <<= 1) {
        int t = __shfl_up_sync(0xffffffffu, s, o);
        if (lane >= o) s += t;
    }
    if (lane == 31) wsum[wid] = s;
    __syncthreads();
    if (wid == 0) {
        int ws = wsum[lane];
#pragma unroll
        for (int o = 1; o < 32; o <<= 1) {
            int t = __shfl_up_sync(0xffffffffu, ws, o);
            if (lane >= o) ws += t;
        }
        wsum[lane] = ws;
    }
    __syncthreads();
    int incl = s + (wid > 0 ? wsum[wid - 1] : 0);
    int blk_total = wsum[31];
    volatile int* pub = (volatile int*)(g_cntpub + n);
    if (threadIdx.x == 0) pub[blockIdx.x] = blk_total + 1;
    if (wid == 0) {
        int off = 0;
        for (int j = lane; j < blockIdx.x; j += 32) {
            int pv;
            do { pv = pub[j]; } while (pv == 0);
            off += pv - 1;
        }
#pragma unroll
        for (int o = 16; o; o >>= 1) off += __shfl_xor_sync(0xffffffffu, off, o);
        if (lane == 0) s_off = off;
    }
    __syncthreads();
    int base = s_off;
    if (i < n) {
        int excl = base + incl - v;
        g_rowptr[i] = excl;
        g_cursor[i] = excl;
    }
    if (blockIdx.x == nblk - 1 && threadIdx.x == SCAN_B - 1)
        g_rowptr[n] = base + incl;
}

__global__ void k_fill(const int* __restrict__ src, const int* __restrict__ dst, int E) {
    int e = blockIdx.x * blockDim.x + threadIdx.x;
    if (e >= E) return;
    int s = src[e], d = dst[e];
    float nm = g_dis[s] * g_dis[d];
    int pos = atomicAdd(&g_cursor[d], 1);
    g_epack[pos] = make_int2(s, __float_as_int(nm));
}

// ---------------- tensor-core GEMM: H16[n,64] = A[n,K] @ W[K,64] -------------
// BK=64 smem chunks: layers 2/3 load everything once (1 sync), layer 1 twice.
// F32 template flag fuses fp32->fp16 conversion into the A tile load.

#define GBM 128
#define GPAD 72   // halves per smem row (144B, conflict-free)

template<int K, bool F32>
__global__ void __launch_bounds__(256) k_gemm(const void* __restrict__ Ap,
                                              const __half* __restrict__ Wt,
                                              __half* __restrict__ H, int n) {
    __shared__ __half As[GBM * GPAD];
    __shared__ __half Bs[64 * GPAD];
    const float*  Af = (const float*)Ap;
    const __half* Ah = (const __half*)Ap;
    int row0 = blockIdx.x * GBM;
    int tid = threadIdx.x, lane = tid & 31, warp = tid >> 5;
    int wm = (warp >> 1) * 32, wn = (warp & 1) * 32;
    int g = lane >> 2, t = lane & 3;

    float d[2][4][4] = {};

#pragma unroll
    for (int kb = 0; kb < K; kb += 64) {
        if (kb > 0) __syncthreads();
        // A tile: 128 rows x 64 halves = 1024 uint4 (4 per thread)
#pragma unroll
        for (int it = 0; it < 4; it++) {
            int idx = tid + it * 256;
            int r = idx >> 3, seg = (idx & 7) * 8;
            if (F32) {
                float4 f0 = make_float4(0.f, 0.f, 0.f, 0.f), f1 = f0;
                if (row0 + r < n) {
                    const float* p = Af + (size_t)(row0 + r) * K + kb + seg;
                    f0 = *(const float4*)p;
                    f1 = *(const float4*)(p + 4);
                }
                __half2 h0 = __floats2half2_rn(f0.x, f0.y);
                __half2 h1 = __floats2half2_rn(f0.z, f0.w);
                __half2 h2 = __floats2half2_rn(f1.x, f1.y);
                __half2 h3 = __floats2half2_rn(f1.z, f1.w);
                uint4 u;
                u.x = *(unsigned*)&h0; u.y = *(unsigned*)&h1;
                u.z = *(unsigned*)&h2; u.w = *(unsigned*)&h3;
                *(uint4*)(As + r * GPAD + seg) = u;
            } else {
                uint4 v = make_uint4(0u, 0u, 0u, 0u);
                if (row0 + r < n)
                    v = *(const uint4*)(Ah + (size_t)(row0 + r) * K + kb + seg);
                *(uint4*)(As + r * GPAD + seg) = v;
            }
        }
        // B tile: 64 rows x 64 halves = 512 uint4 (2 per thread), Wt stride 128
#pragma unroll
        for (int it = 0; it < 2; it++) {
            int idx = tid + it * 256;
            int r = idx >> 3, seg = (idx & 7) * 8;
            *(uint4*)(Bs + r * GPAD + seg) =
                *(const uint4*)(Wt + (size_t)r * 128 + kb + seg);
        }
        __syncthreads();
        // 4 k-subtiles, no intervening syncs
#pragma unroll
        for (int kk = 0; kk < 4; kk++) {
            unsigned a[2][4], b[4][2];
#pragma unroll
            for (int i = 0; i < 2; i++) {
                const __half* ap = As + (wm + i * 16 + g) * GPAD + kk * 16 + t * 2;
                a[i][0] = *(const unsigned*)ap;
                a[i][1] = *(const unsigned*)(ap + 8 * GPAD);
                a[i][2] = *(const unsigned*)(ap + 8);
                a[i][3] = *(const unsigned*)(ap + 8 * GPAD + 8);
            }
#pragma unroll
            for (int j = 0; j < 4; j++) {
                const __half* bp = Bs + (wn + j * 8 + g) * GPAD + kk * 16 + t * 2;
                b[j][0] = *(const unsigned*)bp;
                b[j][1] = *(const unsigned*)(bp + 8);
            }
#pragma unroll
            for (int i = 0; i < 2; i++)
#pragma unroll
                for (int j = 0; j < 4; j++)
                    asm volatile(
                        "mma.sync.aligned.m16n8k16.row.col.f32.f16.f16.f32 "
                        "{%0,%1,%2,%3}, {%4,%5,%6,%7}, {%8,%9}, {%0,%1,%2,%3};"
                        : "+f"(d[i][j][0]), "+f"(d[i][j][1]),
                          "+f"(d[i][j][2]), "+f"(d[i][j][3])
                        : "r"(a[i][0]), "r"(a[i][1]), "r"(a[i][2]), "r"(a[i][3]),
                          "r"(b[j][0]), "r"(b[j][1]));
        }
    }
#pragma unroll
    for (int i = 0; i < 2; i++) {
        int r0 = row0 + wm + i * 16 + g;
#pragma unroll
        for (int j = 0; j < 4; j++) {
            int c = wn + j * 8 + t * 2;
            __half2 lo = __floats2half2_rn(d[i][j][0], d[i][j][1]);
            __half2 hi = __floats2half2_rn(d[i][j][2], d[i][j][3]);
            if (r0 < n)     *(__half2*)(H + (size_t)r0 * F + c) = lo;
            if (r0 + 8 < n) *(__half2*)(H + (size_t)(r0 + 8) * F + c) = hi;
        }
    }
}

// ---------------- CSR aggregate: warp per dst, quarter-warp per edge --------

__device__ __forceinline__ void fma8(float* acc, uint4 u, float nm) {
    __half2* hp = (__half2*)&u;
    float2 f0 = __half22float2(hp[0]);
    float2 f1 = __half22float2(hp[1]);
    float2 f2 = __half22float2(hp[2]);
    float2 f3 = __half22float2(hp[3]);
    acc[0] += nm * f0.x; acc[1] += nm * f0.y;
    acc[2] += nm * f1.x; acc[3] += nm * f1.y;
    acc[4] += nm * f2.x; acc[5] += nm * f2.y;
    acc[6] += nm * f3.x; acc[7] += nm * f3.y;
}

__global__ void k_agg(const __half* __restrict__ h, const float* __restrict__ b,
                      __half* __restrict__ xout, int n) {
    int w = (blockIdx.x * blockDim.x + threadIdx.x) >> 5;
    int lane = threadIdx.x & 31;
    if (w >= n) return;
    int qid = lane >> 3;
    int ql  = lane & 7;

    int beg = g_rowptr[w], end = g_rowptr[w + 1];
    float self = g_dis2[w];
    uint4 selfu = __ldg((const uint4*)(h + (size_t)w * F) + ql);

    float acc[8] = {};
    int k = beg;

    for (; k + 16 <= end; k += 16) {
        int2 e0 = g_epack[k + qid];
        int2 e1 = g_epack[k + 4 + qid];
        int2 e2 = g_epack[k + 8 + qid];
        int2 e3 = g_epack[k + 12 + qid];
        uint4 v0 = __ldg((const uint4*)(h + (size_t)e0.x * F) + ql);
        uint4 v1 = __ldg((const uint4*)(h + (size_t)e1.x * F) + ql);
        uint4 v2 = __ldg((const uint4*)(h + (size_t)e2.x * F) + ql);
        uint4 v3 = __ldg((const uint4*)(h + (size_t)e3.x * F) + ql);
        fma8(acc, v0, __int_as_float(e0.y));
        fma8(acc, v1, __int_as_float(e1.y));
        fma8(acc, v2, __int_as_float(e2.y));
        fma8(acc, v3, __int_as_float(e3.y));
    }
    if (k + 8 <= end) {
        int2 e0 = g_epack[k + qid];
        int2 e1 = g_epack[k + 4 + qid];
        uint4 v0 = __ldg((const uint4*)(h + (size_t)e0.x * F) + ql);
        uint4 v1 = __ldg((const uint4*)(h + (size_t)e1.x * F) + ql);
        fma8(acc, v0, __int_as_float(e0.y));
        fma8(acc, v1, __int_as_float(e1.y));
        k += 8;
    }
    if (k + 4 <= end) {
        int2 e0 = g_epack[k + qid];
        uint4 v0 = __ldg((const uint4*)(h + (size_t)e0.x * F) + ql);
        fma8(acc, v0, __int_as_float(e0.y));
        k += 4;
    }
    if (k + qid < end) {
        int2 e0 = g_epack[k + qid];
        uint4 v0 = __ldg((const uint4*)(h + (size_t)e0.x * F) + ql);
        fma8(acc, v0, __int_as_float(e0.y));
    }
#pragma unroll
    for (int j = 0; j < 8; j++) {
        acc[j] += __shfl_xor_sync(0xffffffffu, acc[j], 8);
        acc[j] += __shfl_xor_sync(0xffffffffu, acc[j], 16);
    }

    fma8(acc, selfu, self);   // self loop

    if (qid == 0) {
        float4 bv0 = __ldg((const float4*)b + ql * 2);
        float4 bv1 = __ldg((const float4*)b + ql * 2 + 1);
        __half2 q0 = __floats2half2_rn(fmaxf(acc[0] + bv0.x, 0.f), fmaxf(acc[1] + bv0.y, 0.f));
        __half2 q1 = __floats2half2_rn(fmaxf(acc[2] + bv0.z, 0.f), fmaxf(acc[3] + bv0.w, 0.f));
        __half2 q2 = __floats2half2_rn(fmaxf(acc[4] + bv1.x, 0.f), fmaxf(acc[5] + bv1.y, 0.f));
        __half2 q3 = __floats2half2_rn(fmaxf(acc[6] + bv1.z, 0.f), fmaxf(acc[7] + bv1.w, 0.f));
        uint4 u;
        u.x = *(unsigned*)&q0; u.y = *(unsigned*)&q1;
        u.z = *(unsigned*)&q2; u.w = *(unsigned*)&q3;
        *(uint4*)(xout + (size_t)w * F + ql * 8) = u;
    }
}

// ---------------- fused pool + MLP (sums x1+x2+x3) ----------------------------

__device__ __forceinline__ int lower_bound_i(const int* __restrict__ a, int n, int key) {
    int lo = 0, hi = n;
    while (lo < hi) {
        int mid = (lo + hi) >> 1;
        if (a[mid] < key) lo = mid + 1; else hi = mid;
    }
    return lo;
}

__global__ void k_poolmlp(const int* __restrict__ batch, int n,
                          const float* __restrict__ Wp1, const float* __restrict__ bp1,
                          const float* __restrict__ Wp2, const float* __restrict__ bp2,
                          float* __restrict__ out) {
    __shared__ int s_range[2];
    __shared__ float p[F], t1[F];
    int g = blockIdx.x, j = threadIdx.x;
    if (j < 2) s_range[j] = lower_bound_i(batch, n, g + j);
    __syncthreads();
    int st = s_range[0], en = s_range[1];
    float acc = 0.f;
    for (int node = st; node < en; node++) {
        size_t o = (size_t)node * F + j;
        acc += __half2float(g_x1[o]) + __half2float(g_x2[o]) + __half2float(g_x3[o]);
    }
    float inv = 1.0f / fmaxf((float)(en - st), 1.0f);
    p[j] = acc * inv;
    __syncthreads();
    float a = bp1[j];
#pragma unroll
    for (int k = 0; k < F; k++) a += p[k] * Wp1[k * F + j];
    t1[j] = fmaxf(a, 0.f);
    __syncthreads();
    if (j < 32) {
        float a2 = bp2[j];
#pragma unroll
        for (int k = 0; k < F; k++) a2 += t1[k] * Wp2[k * 32 + j];
        out[g * 32 + j] = a2;
    }
}

// ---------------- launch -----------------------------------------------------

extern "C" void kernel_launch(void* const* d_in, const int* in_sizes, int n_in,
                              void* d_out, int out_size) {
    const float* x    = (const float*)d_in[0];
    const int*   ei   = (const int*)d_in[1];
    const int*   batch= (const int*)d_in[2];
    const float* W1   = (const float*)d_in[3];
    const float* b1   = (const float*)d_in[4];
    const float* W2   = (const float*)d_in[5];
    const float* b2   = (const float*)d_in[6];
    const float* W3   = (const float*)d_in[7];
    const float* b3   = (const float*)d_in[8];
    const float* Wp1  = (const float*)d_in[9];
    const float* bp1  = (const float*)d_in[10];
    const float* Wp2  = (const float*)d_in[11];
    const float* bp2  = (const float*)d_in[12];
    float* out = (float*)d_out;

    int N = in_sizes[0] / 128;
    int E = in_sizes[1] / 2;
    int G = out_size / 32;
    const int* src = ei;
    const int* dst = ei + E;

    __half *p_h, *p_x1, *p_x2, *p_x3, *p_wt;
    int *p_cnt;
    cudaGetSymbolAddress((void**)&p_h, g_h16);
    cudaGetSymbolAddress((void**)&p_x1, g_x1);
    cudaGetSymbolAddress((void**)&p_x2, g_x2);
    cudaGetSymbolAddress((void**)&p_x3, g_x3);
    cudaGetSymbolAddress((void**)&p_wt, g_w16t);
    cudaGetSymbolAddress((void**)&p_cnt, g_cntpub);

    __half* wt1 = p_wt;
    __half* wt2 = p_wt + 64 * 128;
    __half* wt3 = p_wt + 2 * 64 * 128;

    const int T = 256;
    int nblk = (N + SCAN_B - 1) / SCAN_B;

    cudaMemsetAsync(p_cnt, 0, ((size_t)N + nblk) * sizeof(int));

    int nH = (E + T - 1) / T;
    k_prep<<<64 + nH, T>>>(W1, W2, W3, dst, E);
    k_scan<<<nblk, SCAN_B>>>(N, nblk);
    k_fill<<<(E + T - 1) / T, T>>>(src, dst, E);

    int gemm_blocks = (N + GBM - 1) / GBM;
    int agg_blocks  = (N + 7) / 8;

    // layer 1 (fp32 input, conversion fused into tile load)
    k_gemm<128, true><<<gemm_blocks, T>>>(x, wt1, p_h, N);
    k_agg<<<agg_blocks, T>>>(p_h, b1, p_x1, N);
    // layer 2
    k_gemm<64, false><<<gemm_blocks, T>>>(p_x1, wt2, p_h, N);
    k_agg<<<agg_blocks, T>>>(p_h, b2, p_x2, N);
    // layer 3
    k_gemm<64, false><<<gemm_blocks, T>>>(p_x2, wt3, p_h, N);
    k_agg<<<agg_blocks, T>>>(p_h, b3, p_x3, N);

    // fused pooling + MLP
    k_poolmlp<<<G, F>>>(batch, N, Wp1, bp1, Wp2, bp2, out);
}